// round 1
// baseline (speedup 1.0000x reference)
#include <cuda_runtime.h>
#include <math.h>

// ----------------------------------------------------------------------------
// UPTRec forward: embed -> batched k-means(16,10 iters) -> 2x cluster-masked
// transformer layer -> final LN -> pos/neg logits.
// Round 1: all fp32, SIMT GEMMs, smem-resident attention, exact-match k-means.
// ----------------------------------------------------------------------------

constexpr int Bn   = 512;
constexpr int Tn   = 256;
constexpr int Cn   = 256;
constexpr int Hn   = 4;
constexpr int DHn  = 64;
constexpr int Ln   = 2;
constexpr int Kcl  = 16;
constexpr int ITEM_H = 192;
constexpr int USER_H = 64;
constexpr int NTOK = Bn * Tn;          // 131072
constexpr int NC   = NTOK * Cn;        // 33,554,432

// Scratch (device globals: no allocation allowed)
__device__ float g_x[NC];
__device__ float g_qin[NC];
__device__ float g_Q[NC];
__device__ float g_K[NC];
__device__ float g_V[NC];
__device__ float g_attn[NC];
__device__ float g_h1[NC];
__device__ float g_out[NC];
__device__ float g_ulat[Bn * USER_H];
__device__ int   g_ids[NTOK];

// ----------------------------------------------------------------------------
// Embedding: x[b,t,:] = concat(item_emb[seq], user_emb[uid]) + pos_emb[t]
// ----------------------------------------------------------------------------
__global__ void embed_kernel(const int* __restrict__ uid,
                             const int* __restrict__ seq,
                             const float* __restrict__ item_emb,
                             const float* __restrict__ user_emb,
                             const float* __restrict__ pos_emb) {
    int idx = blockIdx.x * blockDim.x + threadIdx.x;
    if (idx >= NC) return;
    int i = idx >> 8;           // token index (Cn = 256)
    int c = idx & 255;
    int b = i >> 8;             // Tn = 256
    int t = i & 255;
    float v;
    if (c < ITEM_H) v = item_emb[seq[i] * ITEM_H + c];
    else            v = user_emb[uid[b] * USER_H + (c - ITEM_H)];
    g_x[idx] = v + pos_emb[t * Cn + c];
}

__global__ void ulat_kernel(const int* __restrict__ uid,
                            const float* __restrict__ user_emb) {
    int b = blockIdx.x;
    g_ulat[b * USER_H + threadIdx.x] = user_emb[uid[b] * USER_H + threadIdx.x];
}

__global__ void mask_kernel(const int* __restrict__ seq) {
    int idx = blockIdx.x * blockDim.x + threadIdx.x;
    if (idx >= NC) return;
    int i = idx >> 8;
    if (seq[i] == 0) g_x[idx] = 0.0f;
}

// ----------------------------------------------------------------------------
// Batched Lloyd k-means: one block per batch. Matches reference:
// d = x_sq - 2*dot + c_sq; argmin first-occurrence; centroid = sum/max(cnt,1)
// where cnt>0 else old; 10 update iters + final assign.
// ----------------------------------------------------------------------------
__device__ __forceinline__ float warp_sum(float v) {
    v += __shfl_xor_sync(0xffffffffu, v, 16);
    v += __shfl_xor_sync(0xffffffffu, v, 8);
    v += __shfl_xor_sync(0xffffffffu, v, 4);
    v += __shfl_xor_sync(0xffffffffu, v, 2);
    v += __shfl_xor_sync(0xffffffffu, v, 1);
    return v;
}

__global__ __launch_bounds__(256) void kmeans_kernel() {
    __shared__ float cent[Kcl * Cn];   // 16 KB
    __shared__ float xsq[Tn];
    __shared__ float csq[Kcl];
    __shared__ int   sids[Tn];
    __shared__ int   cnt[Kcl];

    const int b    = blockIdx.x;
    const int tid  = threadIdx.x;
    const int lane = tid & 31;
    const int warp = tid >> 5;
    const float* Xb = g_x + b * Tn * Cn;

    // init centroids = first 16 rows (contiguous)
    for (int i = tid; i < Kcl * Cn; i += 256) cent[i] = Xb[i];

    // x_sq per row (warp per 32 rows, lane-strided coalesced)
    for (int r = 0; r < 32; r++) {
        int t = warp * 32 + r;
        float s = 0.f;
        #pragma unroll
        for (int j = 0; j < 8; j++) {
            float xv = Xb[t * Cn + lane + 32 * j];
            s += xv * xv;
        }
        s = warp_sum(s);
        if (lane == 0) xsq[t] = s;
    }
    __syncthreads();

    for (int iter = 0; iter <= 10; iter++) {
        // centroid squared norms
        if (tid < Kcl) {
            float s = 0.f;
            for (int c = 0; c < Cn; c++) { float v = cent[tid * Cn + c]; s += v * v; }
            csq[tid] = s;
        }
        __syncthreads();

        // assign
        for (int r = 0; r < 32; r++) {
            int t = warp * 32 + r;
            float xv[8];
            #pragma unroll
            for (int j = 0; j < 8; j++) xv[j] = Xb[t * Cn + lane + 32 * j];
            float best = 3.4e38f; int bi = 0;
            #pragma unroll
            for (int k = 0; k < Kcl; k++) {
                float p = 0.f;
                #pragma unroll
                for (int j = 0; j < 8; j++) p += xv[j] * cent[k * Cn + lane + 32 * j];
                p = warp_sum(p);
                float d = xsq[t] - 2.0f * p + csq[k];
                if (d < best) { best = d; bi = k; }   // first-min tie-break
            }
            if (lane == 0) sids[t] = bi;
        }
        __syncthreads();

        if (iter == 10) break;

        // counts
        if (tid < Kcl) cnt[tid] = 0;
        __syncthreads();
        atomicAdd(&cnt[sids[tid]], 1);
        __syncthreads();

        // per-column sums + centroid update (thread = column)
        {
            const int c = tid;
            float acc[Kcl];
            #pragma unroll
            for (int k = 0; k < Kcl; k++) acc[k] = 0.f;
            for (int t = 0; t < Tn; t++) {
                float v = Xb[t * Cn + c];
                int id = sids[t];
                #pragma unroll
                for (int k = 0; k < Kcl; k++) acc[k] += (id == k) ? v : 0.f;
            }
            __syncthreads();   // everyone done reading old cent for csq? (csq already copied)
            #pragma unroll
            for (int k = 0; k < Kcl; k++) {
                if (cnt[k] > 0) cent[k * Cn + c] = acc[k] / fmaxf((float)cnt[k], 1.0f);
            }
        }
        __syncthreads();
    }

    g_ids[b * Tn + tid] = sids[tid];
}

// ----------------------------------------------------------------------------
// LayerNorm: warp per row of 256
// ----------------------------------------------------------------------------
__global__ __launch_bounds__(256) void ln_kernel(const float* __restrict__ in,
                                                 float* __restrict__ out,
                                                 const float* __restrict__ g,
                                                 const float* __restrict__ bb) {
    int lane = threadIdx.x & 31, warp = threadIdx.x >> 5;
    int row = blockIdx.x * 8 + warp;
    const float* r = in + row * Cn;
    float v[8];
    #pragma unroll
    for (int j = 0; j < 8; j++) v[j] = r[lane + 32 * j];
    float s = 0.f;
    #pragma unroll
    for (int j = 0; j < 8; j++) s += v[j];
    s = warp_sum(s);
    float mu = s * (1.0f / 256.0f);
    float q = 0.f;
    #pragma unroll
    for (int j = 0; j < 8; j++) { float d = v[j] - mu; q += d * d; }
    q = warp_sum(q);
    float rinv = rsqrtf(q * (1.0f / 256.0f) + 1e-8f);
    #pragma unroll
    for (int j = 0; j < 8; j++) {
        int c = lane + 32 * j;
        out[row * Cn + c] = g[c] * (v[j] - mu) * rinv + bb[c];
    }
}

// ----------------------------------------------------------------------------
// SGEMM: C[m,n] = sum_k A[m,k] * W[k,n];  M=131072, K=N=256.
// BM=128, BN=64, BK=16, 256 threads, 8x4 per thread.
// MODE 0: plain   1: (acc+res)*keep   2: relu(acc+bias)   3: (acc+bias+res)*keep
// ----------------------------------------------------------------------------
template <int MODE>
__global__ __launch_bounds__(256) void sgemm_kernel(const float* __restrict__ A,
                                                    const float* __restrict__ W,
                                                    float* __restrict__ Cout,
                                                    const float* __restrict__ res,
                                                    const float* __restrict__ bias,
                                                    const int* __restrict__ seq) {
    __shared__ float As[16][128];
    __shared__ float Bs[16][64];

    const int n0 = blockIdx.x * 64;
    const int m0 = blockIdx.y * 128;
    const int tid = threadIdx.x;
    const int tx = tid & 15;     // 16 col groups * 4
    const int ty = tid >> 4;     // 16 row groups * 8

    float acc[8][4];
    #pragma unroll
    for (int i = 0; i < 8; i++)
        #pragma unroll
        for (int j = 0; j < 4; j++) acc[i][j] = 0.f;

    for (int k0 = 0; k0 < 256; k0 += 16) {
        // A tile: 128x16 -> As[k][m]
        #pragma unroll
        for (int i = tid; i < 512; i += 256) {
            int row = i >> 2;
            int c4  = i & 3;
            float4 v = *(const float4*)(A + (m0 + row) * 256 + k0 + c4 * 4);
            As[c4 * 4 + 0][row] = v.x;
            As[c4 * 4 + 1][row] = v.y;
            As[c4 * 4 + 2][row] = v.z;
            As[c4 * 4 + 3][row] = v.w;
        }
        // W tile: 16x64
        {
            int row = tid >> 4;
            int c4  = tid & 15;
            float4 v = *(const float4*)(W + (k0 + row) * 256 + n0 + c4 * 4);
            *(float4*)&Bs[row][c4 * 4] = v;
        }
        __syncthreads();

        #pragma unroll
        for (int kk = 0; kk < 16; kk++) {
            float4 a0 = *(const float4*)&As[kk][ty * 8];
            float4 a1 = *(const float4*)&As[kk][ty * 8 + 4];
            float4 bv = *(const float4*)&Bs[kk][tx * 4];
            float a[8] = {a0.x, a0.y, a0.z, a0.w, a1.x, a1.y, a1.z, a1.w};
            float bb4[4] = {bv.x, bv.y, bv.z, bv.w};
            #pragma unroll
            for (int i = 0; i < 8; i++)
                #pragma unroll
                for (int j = 0; j < 4; j++) acc[i][j] += a[i] * bb4[j];
        }
        __syncthreads();
    }

    #pragma unroll
    for (int i = 0; i < 8; i++) {
        int m = m0 + ty * 8 + i;
        int n = n0 + tx * 4;
        float keep = 1.0f;
        if (MODE == 1 || MODE == 3) keep = (seq[m] != 0) ? 1.0f : 0.0f;
        float4 o;
        float v0 = acc[i][0], v1 = acc[i][1], v2 = acc[i][2], v3 = acc[i][3];
        if (MODE == 2 || MODE == 3) {
            v0 += bias[n + 0]; v1 += bias[n + 1]; v2 += bias[n + 2]; v3 += bias[n + 3];
        }
        if (MODE == 1 || MODE == 3) {
            const float4 rv = *(const float4*)(res + m * 256 + n);
            v0 = (v0 + rv.x) * keep; v1 = (v1 + rv.y) * keep;
            v2 = (v2 + rv.z) * keep; v3 = (v3 + rv.w) * keep;
        }
        if (MODE == 2) {
            v0 = fmaxf(v0, 0.f); v1 = fmaxf(v1, 0.f);
            v2 = fmaxf(v2, 0.f); v3 = fmaxf(v3, 0.f);
        }
        o.x = v0; o.y = v1; o.z = v2; o.w = v3;
        *(float4*)(Cout + m * 256 + n) = o;
    }
}

// ----------------------------------------------------------------------------
// Cluster-masked attention: block per (b,h). K/V tiles in smem (128 KB),
// online softmax, one q row per thread.
// ----------------------------------------------------------------------------
__global__ __launch_bounds__(256, 1) void attn_kernel(const int* __restrict__ seq) {
    extern __shared__ float sm[];
    float* Ks = sm;                    // [256][64]
    float* Vs = sm + Tn * DHn;         // [256][64]
    __shared__ int sids[Tn];

    const int b = blockIdx.x >> 2;     // Hn = 4
    const int h = blockIdx.x & 3;
    const int tid = threadIdx.x;

    for (int idx = tid; idx < Tn * DHn; idx += 256) {
        int t = idx >> 6, d = idx & 63;
        int gi = (b * Tn + t) * Cn + h * DHn + d;
        Ks[idx] = g_K[gi];
        Vs[idx] = g_V[gi];
    }
    sids[tid] = g_ids[b * Tn + tid];
    __syncthreads();

    const int q = tid;
    float4 qv[16];
    {
        const float4* qp = (const float4*)(g_Q + (b * Tn + q) * Cn + h * DHn);
        #pragma unroll
        for (int j = 0; j < 16; j++) qv[j] = qp[j];
    }
    const int  myid   = sids[q];
    const bool qvalid = (seq[b * Tn + q] != 0);

    float m = -1e30f, ssum = 0.f;
    float4 accv[16];
    #pragma unroll
    for (int j = 0; j < 16; j++) accv[j] = make_float4(0.f, 0.f, 0.f, 0.f);

    for (int k = 0; k < Tn; k++) {
        float s;
        if (qvalid && sids[k] == myid) {
            const float4* kp = (const float4*)&Ks[k * DHn];
            float dot = 0.f;
            #pragma unroll
            for (int j = 0; j < 16; j++) {
                float4 kvv = kp[j];
                dot += qv[j].x * kvv.x + qv[j].y * kvv.y + qv[j].z * kvv.z + qv[j].w * kvv.w;
            }
            s = dot * 0.125f;
        } else {
            s = -1e9f;
        }
        float nm = fmaxf(m, s);
        float cs = __expf(m - nm);
        float p  = __expf(s - nm);
        ssum = ssum * cs + p;
        const float4* vp = (const float4*)&Vs[k * DHn];
        #pragma unroll
        for (int j = 0; j < 16; j++) {
            float4 vv = vp[j];
            accv[j].x = accv[j].x * cs + p * vv.x;
            accv[j].y = accv[j].y * cs + p * vv.y;
            accv[j].z = accv[j].z * cs + p * vv.z;
            accv[j].w = accv[j].w * cs + p * vv.w;
        }
        m = nm;
    }

    float inv = 1.0f / ssum;
    float4* op = (float4*)(g_attn + (b * Tn + q) * Cn + h * DHn);
    #pragma unroll
    for (int j = 0; j < 16; j++) {
        op[j] = make_float4(accv[j].x * inv, accv[j].y * inv, accv[j].z * inv, accv[j].w * inv);
    }
}

// ----------------------------------------------------------------------------
// Logits: warp per token
// ----------------------------------------------------------------------------
__global__ __launch_bounds__(256) void logits_kernel(const int* __restrict__ pos_seqs,
                                                     const int* __restrict__ neg_seqs,
                                                     const float* __restrict__ item_emb,
                                                     float* __restrict__ out) {
    int lane = threadIdx.x & 31, warp = threadIdx.x >> 5;
    int i = blockIdx.x * 8 + warp;
    const float* o  = g_out + i * Cn;
    const float* ul = g_ulat + (i >> 8) * USER_H;
    const float* pe = item_emb + pos_seqs[i] * ITEM_H;
    const float* ne = item_emb + neg_seqs[i] * ITEM_H;
    float sp = 0.f, sn = 0.f;
    for (int c = lane; c < ITEM_H; c += 32) {
        float ov = o[c];
        sp += ov * pe[c];
        sn += ov * ne[c];
    }
    for (int j = lane; j < USER_H; j += 32) {
        float ov = o[ITEM_H + j];
        float u  = ul[j];
        sp += ov * u;
        sn += ov * u;
    }
    sp = warp_sum(sp);
    sn = warp_sum(sn);
    if (lane == 0) {
        out[i]        = sp;
        out[NTOK + i] = sn;
    }
}

// ----------------------------------------------------------------------------
// Launch
// ----------------------------------------------------------------------------
extern "C" void kernel_launch(void* const* d_in, const int* in_sizes, int n_in,
                              void* d_out, int out_size) {
    const int*   uid      = (const int*)d_in[0];
    const int*   seq      = (const int*)d_in[1];
    const int*   pos_seqs = (const int*)d_in[2];
    const int*   neg_seqs = (const int*)d_in[3];
    const float* item_emb = (const float*)d_in[4];
    const float* user_emb = (const float*)d_in[5];
    const float* pos_emb  = (const float*)d_in[6];
    const float* Wq = (const float*)d_in[7];
    const float* Wk = (const float*)d_in[8];
    const float* Wv = (const float*)d_in[9];
    const float* Wo = (const float*)d_in[10];
    const float* ln1g = (const float*)d_in[11];
    const float* ln1b = (const float*)d_in[12];
    const float* ln2g = (const float*)d_in[13];
    const float* ln2b = (const float*)d_in[14];
    const float* W1 = (const float*)d_in[15];
    const float* b1 = (const float*)d_in[16];
    const float* W2 = (const float*)d_in[17];
    const float* b2 = (const float*)d_in[18];
    const float* lnfg = (const float*)d_in[19];
    const float* lnfb = (const float*)d_in[20];
    float* out = (float*)d_out;

    float *px, *pqin, *pQ, *pK, *pV, *pattn, *ph1, *pout;
    cudaGetSymbolAddress((void**)&px,    g_x);
    cudaGetSymbolAddress((void**)&pqin,  g_qin);
    cudaGetSymbolAddress((void**)&pQ,    g_Q);
    cudaGetSymbolAddress((void**)&pK,    g_K);
    cudaGetSymbolAddress((void**)&pV,    g_V);
    cudaGetSymbolAddress((void**)&pattn, g_attn);
    cudaGetSymbolAddress((void**)&ph1,   g_h1);
    cudaGetSymbolAddress((void**)&pout,  g_out);

    const int attn_smem = 2 * Tn * DHn * (int)sizeof(float);  // 128 KB
    cudaFuncSetAttribute(attn_kernel, cudaFuncAttributeMaxDynamicSharedMemorySize, attn_smem);

    // 1) embedding
    embed_kernel<<<NC / 256, 256>>>(uid, seq, item_emb, user_emb, pos_emb);
    ulat_kernel<<<Bn, USER_H>>>(uid, user_emb);

    // 2) k-means on unmasked x
    kmeans_kernel<<<Bn, 256>>>();

    // 3) mask pad rows
    mask_kernel<<<NC / 256, 256>>>(seq);

    const dim3 ggrid(Cn / 64, NTOK / 128);

    for (int l = 0; l < Ln; l++) {
        const float* wq = Wq + l * Cn * Cn;
        const float* wk = Wk + l * Cn * Cn;
        const float* wv = Wv + l * Cn * Cn;
        const float* wo = Wo + l * Cn * Cn;
        const float* w1 = W1 + l * Cn * Cn;
        const float* w2 = W2 + l * Cn * Cn;

        // q_in = LN1(x)
        ln_kernel<<<NTOK / 8, 256>>>(px, pqin, ln1g + l * Cn, ln1b + l * Cn);
        // projections
        sgemm_kernel<0><<<ggrid, 256>>>(pqin, wq, pQ, nullptr, nullptr, nullptr);
        sgemm_kernel<0><<<ggrid, 256>>>(px,   wk, pK, nullptr, nullptr, nullptr);
        sgemm_kernel<0><<<ggrid, 256>>>(px,   wv, pV, nullptr, nullptr, nullptr);
        // masked attention
        attn_kernel<<<Bn * Hn, 256, attn_smem>>>(seq);
        // x = (q_in + attn @ Wo) * keep
        sgemm_kernel<1><<<ggrid, 256>>>(pattn, wo, px, pqin, nullptr, seq);
        // f = LN2(x)
        ln_kernel<<<NTOK / 8, 256>>>(px, pqin, ln2g + l * Cn, ln2b + l * Cn);
        // h1 = relu(f @ W1 + b1)
        sgemm_kernel<2><<<ggrid, 256>>>(pqin, w1, ph1, nullptr, b1 + l * Cn, nullptr);
        // x = (x + h1 @ W2 + b2) * keep
        sgemm_kernel<3><<<ggrid, 256>>>(ph1, w2, px, px, b2 + l * Cn, seq);
    }

    // final LN
    ln_kernel<<<NTOK / 8, 256>>>(px, pout, lnfg, lnfb);

    // logits
    logits_kernel<<<NTOK / 8, 256>>>(pos_seqs, neg_seqs, item_emb, out);
}

// round 3
// speedup vs baseline: 2.1411x; 2.1411x over previous
#include <cuda_runtime.h>
#include <cuda_fp16.h>
#include <stdint.h>
#include <math.h>

// ----------------------------------------------------------------------------
// UPTRec forward. Round 3 (= round 2 + missing <stdint.h>):
// fp16 mma.sync GEMMs (fp32 accum, fp32 residuals), cluster-bucketed
// attention, exact fp32 k-means.
// ----------------------------------------------------------------------------

constexpr int Bn   = 512;
constexpr int Tn   = 256;
constexpr int Cn   = 256;
constexpr int Hn   = 4;
constexpr int DHn  = 64;
constexpr int Ln   = 2;
constexpr int Kcl  = 16;
constexpr int ITEM_H = 192;
constexpr int USER_H = 64;
constexpr int NTOK = Bn * Tn;          // 131072
constexpr int NC   = NTOK * Cn;        // 33,554,432

// fp32 scratch
__device__ float g_x[NC];
__device__ float g_qin[NC];
__device__ float g_Q[NC];
__device__ float g_K[NC];
__device__ float g_V[NC];
__device__ float g_out[NC];
__device__ float g_ulat[Bn * USER_H];
__device__ int   g_ids[NTOK];
// fp16 mirrors (GEMM A operands)
__device__ __align__(16) __half g_xh[NC];
__device__ __align__(16) __half g_qinh[NC];
__device__ __align__(16) __half g_attnh[NC];
__device__ __align__(16) __half g_h1h[NC];
// fp16 weights: [6 arrays][L][C][C] order q,k,v,o,W1,W2
__device__ __align__(16) __half g_Wh[6 * Ln * Cn * Cn];

// ----------------------------------------------------------------------------
__device__ __forceinline__ float warp_sum(float v) {
    v += __shfl_xor_sync(0xffffffffu, v, 16);
    v += __shfl_xor_sync(0xffffffffu, v, 8);
    v += __shfl_xor_sync(0xffffffffu, v, 4);
    v += __shfl_xor_sync(0xffffffffu, v, 2);
    v += __shfl_xor_sync(0xffffffffu, v, 1);
    return v;
}

// ----------------------------------------------------------------------------
// Embedding
// ----------------------------------------------------------------------------
__global__ void embed_kernel(const int* __restrict__ uid,
                             const int* __restrict__ seq,
                             const float* __restrict__ item_emb,
                             const float* __restrict__ user_emb,
                             const float* __restrict__ pos_emb) {
    int idx = blockIdx.x * blockDim.x + threadIdx.x;
    if (idx >= NC) return;
    int i = idx >> 8;
    int c = idx & 255;
    int b = i >> 8;
    int t = i & 255;
    float v;
    if (c < ITEM_H) v = item_emb[seq[i] * ITEM_H + c];
    else            v = user_emb[uid[b] * USER_H + (c - ITEM_H)];
    g_x[idx] = v + pos_emb[t * Cn + c];
}

__global__ void ulat_kernel(const int* __restrict__ uid,
                            const float* __restrict__ user_emb) {
    int b = blockIdx.x;
    g_ulat[b * USER_H + threadIdx.x] = user_emb[uid[b] * USER_H + threadIdx.x];
}

// mask pad rows; emit fp16 mirror of masked x
__global__ void mask_kernel(const int* __restrict__ seq) {
    int idx = blockIdx.x * blockDim.x + threadIdx.x;
    if (idx >= NC) return;
    int i = idx >> 8;
    float v = g_x[idx];
    if (seq[i] == 0) v = 0.0f;
    g_x[idx]  = v;
    g_xh[idx] = __float2half(v);
}

// fp32 -> fp16 weight conversion (6 arrays of L*C*C each)
__global__ void convw_kernel(const float* __restrict__ Wq, const float* __restrict__ Wk,
                             const float* __restrict__ Wv, const float* __restrict__ Wo,
                             const float* __restrict__ W1, const float* __restrict__ W2) {
    int idx = blockIdx.x * blockDim.x + threadIdx.x;
    const int per = Ln * Cn * Cn;            // 131072
    if (idx >= 6 * per) return;
    int a = idx / per;
    int r = idx - a * per;
    const float* s;
    switch (a) {
        case 0: s = Wq; break; case 1: s = Wk; break; case 2: s = Wv; break;
        case 3: s = Wo; break; case 4: s = W1; break; default: s = W2; break;
    }
    g_Wh[idx] = __float2half(s[r]);
}

// ----------------------------------------------------------------------------
// Batched Lloyd k-means (exact fp32, matches reference argmin semantics)
// ----------------------------------------------------------------------------
__global__ __launch_bounds__(256) void kmeans_kernel() {
    __shared__ float cent[Kcl * Cn];
    __shared__ float xsq[Tn];
    __shared__ float csq[Kcl];
    __shared__ int   sids[Tn];
    __shared__ int   cnt[Kcl];

    const int b    = blockIdx.x;
    const int tid  = threadIdx.x;
    const int lane = tid & 31;
    const int warp = tid >> 5;
    const float* Xb = g_x + b * Tn * Cn;

    for (int i = tid; i < Kcl * Cn; i += 256) cent[i] = Xb[i];

    for (int r = 0; r < 32; r++) {
        int t = warp * 32 + r;
        float s = 0.f;
        #pragma unroll
        for (int j = 0; j < 8; j++) {
            float xv = Xb[t * Cn + lane + 32 * j];
            s += xv * xv;
        }
        s = warp_sum(s);
        if (lane == 0) xsq[t] = s;
    }
    __syncthreads();

    for (int iter = 0; iter <= 10; iter++) {
        if (tid < Kcl) {
            float s = 0.f;
            for (int c = 0; c < Cn; c++) { float v = cent[tid * Cn + c]; s += v * v; }
            csq[tid] = s;
        }
        __syncthreads();

        for (int r = 0; r < 32; r++) {
            int t = warp * 32 + r;
            float xv[8];
            #pragma unroll
            for (int j = 0; j < 8; j++) xv[j] = Xb[t * Cn + lane + 32 * j];
            float best = 3.4e38f; int bi = 0;
            #pragma unroll
            for (int k = 0; k < Kcl; k++) {
                float p = 0.f;
                #pragma unroll
                for (int j = 0; j < 8; j++) p += xv[j] * cent[k * Cn + lane + 32 * j];
                p = warp_sum(p);
                float d = xsq[t] - 2.0f * p + csq[k];
                if (d < best) { best = d; bi = k; }
            }
            if (lane == 0) sids[t] = bi;
        }
        __syncthreads();

        if (iter == 10) break;

        if (tid < Kcl) cnt[tid] = 0;
        __syncthreads();
        atomicAdd(&cnt[sids[tid]], 1);
        __syncthreads();

        {
            const int c = tid;
            float acc[Kcl];
            #pragma unroll
            for (int k = 0; k < Kcl; k++) acc[k] = 0.f;
            for (int t = 0; t < Tn; t++) {
                float v = Xb[t * Cn + c];
                int id = sids[t];
                #pragma unroll
                for (int k = 0; k < Kcl; k++) acc[k] += (id == k) ? v : 0.f;
            }
            __syncthreads();
            #pragma unroll
            for (int k = 0; k < Kcl; k++) {
                if (cnt[k] > 0) cent[k * Cn + c] = acc[k] / fmaxf((float)cnt[k], 1.0f);
            }
        }
        __syncthreads();
    }

    g_ids[b * Tn + tid] = sids[tid];
}

// ----------------------------------------------------------------------------
// LayerNorm: warp per row; fp32 out + fp16 mirror
// ----------------------------------------------------------------------------
__global__ __launch_bounds__(256) void ln_kernel(const float* __restrict__ in,
                                                 float* __restrict__ out,
                                                 __half* __restrict__ outh,
                                                 const float* __restrict__ g,
                                                 const float* __restrict__ bb) {
    int lane = threadIdx.x & 31, warp = threadIdx.x >> 5;
    int row = blockIdx.x * 8 + warp;
    const float* r = in + row * Cn;
    float v[8];
    #pragma unroll
    for (int j = 0; j < 8; j++) v[j] = r[lane + 32 * j];
    float s = 0.f;
    #pragma unroll
    for (int j = 0; j < 8; j++) s += v[j];
    s = warp_sum(s);
    float mu = s * (1.0f / 256.0f);
    float q = 0.f;
    #pragma unroll
    for (int j = 0; j < 8; j++) { float d = v[j] - mu; q += d * d; }
    q = warp_sum(q);
    float rinv = rsqrtf(q * (1.0f / 256.0f) + 1e-8f);
    #pragma unroll
    for (int j = 0; j < 8; j++) {
        int c = lane + 32 * j;
        float o = g[c] * (v[j] - mu) * rinv + bb[c];
        out[row * Cn + c]  = o;
        outh[row * Cn + c] = __float2half(o);
    }
}

// ----------------------------------------------------------------------------
// fp16 tensor-core GEMM: C[M=131072, N=256] = A @ W, K=256.
// BM=128, BN=128, BK=32, 256 threads (8 warps, 2x4), warp tile 64x32.
// MODE 0: fp32 out
// MODE 1: fp32 out = (acc + res) * keep
// MODE 2: fp16 out = relu(acc + bias)
// MODE 3: fp32 out = (acc + bias + res) * keep, fp16 mirror
// ----------------------------------------------------------------------------
__device__ __forceinline__ void ldsm4(uint32_t* r, uint32_t addr) {
    asm volatile("ldmatrix.sync.aligned.m8n8.x4.shared.b16 {%0,%1,%2,%3}, [%4];"
        : "=r"(r[0]), "=r"(r[1]), "=r"(r[2]), "=r"(r[3]) : "r"(addr));
}
__device__ __forceinline__ void ldsm4t(uint32_t* r, uint32_t addr) {
    asm volatile("ldmatrix.sync.aligned.m8n8.x4.trans.shared.b16 {%0,%1,%2,%3}, [%4];"
        : "=r"(r[0]), "=r"(r[1]), "=r"(r[2]), "=r"(r[3]) : "r"(addr));
}
__device__ __forceinline__ void mma16816(float* c, const uint32_t* a, const uint32_t* b) {
    asm volatile("mma.sync.aligned.m16n8k16.row.col.f32.f16.f16.f32 "
        "{%0,%1,%2,%3}, {%4,%5,%6,%7}, {%8,%9}, {%0,%1,%2,%3};"
        : "+f"(c[0]), "+f"(c[1]), "+f"(c[2]), "+f"(c[3])
        : "r"(a[0]), "r"(a[1]), "r"(a[2]), "r"(a[3]), "r"(b[0]), "r"(b[1]));
}

constexpr int BKg = 32;
constexpr int APAD = 8;   // As row = 40 halves
constexpr int BPAD = 8;   // Bs row = 136 halves

template <int MODE>
__global__ __launch_bounds__(256, 1) void hgemm_kernel(const __half* __restrict__ A,
                                                       const __half* __restrict__ W,
                                                       float* __restrict__ Cout,
                                                       __half* __restrict__ CoutH,
                                                       const float* __restrict__ res,
                                                       const float* __restrict__ bias,
                                                       const int* __restrict__ seq) {
    __shared__ __half As[128][BKg + APAD];
    __shared__ __half Bs[BKg][128 + BPAD];

    const int tid  = threadIdx.x;
    const int lane = tid & 31;
    const int warp = tid >> 5;
    const int wm   = warp >> 2;          // 0..1
    const int wn   = warp & 3;           // 0..3
    const int m0   = blockIdx.y * 128;
    const int n0   = blockIdx.x * 128;

    float acc[4][4][4];
    #pragma unroll
    for (int i = 0; i < 4; i++)
        #pragma unroll
        for (int j = 0; j < 4; j++)
            #pragma unroll
            for (int v = 0; v < 4; v++) acc[i][j][v] = 0.f;

    const int a_row0 = tid >> 2,  a_cs0 = tid & 3;
    const int a_row1 = (tid + 256) >> 2, a_cs1 = (tid + 256) & 3;
    const int b_row0 = tid >> 4,  b_cs0 = tid & 15;
    const int b_row1 = (tid + 256) >> 4, b_cs1 = (tid + 256) & 15;

    uint4 pa0, pa1, pb0, pb1;
    {
        pa0 = *(const uint4*)(A + (m0 + a_row0) * 256 + a_cs0 * 8);
        pa1 = *(const uint4*)(A + (m0 + a_row1) * 256 + a_cs1 * 8);
        pb0 = *(const uint4*)(W + b_row0 * 256 + n0 + b_cs0 * 8);
        pb1 = *(const uint4*)(W + b_row1 * 256 + n0 + b_cs1 * 8);
    }
    *(uint4*)&As[a_row0][a_cs0 * 8] = pa0;
    *(uint4*)&As[a_row1][a_cs1 * 8] = pa1;
    *(uint4*)&Bs[b_row0][b_cs0 * 8] = pb0;
    *(uint4*)&Bs[b_row1][b_cs1 * 8] = pb1;
    __syncthreads();

    uint32_t as_base = (uint32_t)__cvta_generic_to_shared(&As[0][0]);
    uint32_t bs_base = (uint32_t)__cvta_generic_to_shared(&Bs[0][0]);

    for (int it = 0; it < 8; it++) {
        if (it < 7) {
            int k0 = (it + 1) * BKg;
            pa0 = *(const uint4*)(A + (m0 + a_row0) * 256 + k0 + a_cs0 * 8);
            pa1 = *(const uint4*)(A + (m0 + a_row1) * 256 + k0 + a_cs1 * 8);
            pb0 = *(const uint4*)(W + (k0 + b_row0) * 256 + n0 + b_cs0 * 8);
            pb1 = *(const uint4*)(W + (k0 + b_row1) * 256 + n0 + b_cs1 * 8);
        }
        #pragma unroll
        for (int kk = 0; kk < BKg; kk += 16) {
            uint32_t aF[4][4];
            uint32_t bF[4][2];
            #pragma unroll
            for (int mt = 0; mt < 4; mt++) {
                int row = wm * 64 + mt * 16 + (lane & 15);
                int col = kk + (lane >> 4) * 8;
                ldsm4(aF[mt], as_base + (uint32_t)((row * (BKg + APAD) + col) * 2));
            }
            #pragma unroll
            for (int np = 0; np < 2; np++) {
                int k = kk + (lane & 15);
                int n = wn * 32 + np * 16 + (lane >> 4) * 8;
                uint32_t r[4];
                ldsm4t(r, bs_base + (uint32_t)((k * (128 + BPAD) + n) * 2));
                bF[np * 2][0] = r[0]; bF[np * 2][1] = r[1];
                bF[np * 2 + 1][0] = r[2]; bF[np * 2 + 1][1] = r[3];
            }
            #pragma unroll
            for (int mt = 0; mt < 4; mt++)
                #pragma unroll
                for (int nt = 0; nt < 4; nt++)
                    mma16816(acc[mt][nt], aF[mt], bF[nt]);
        }
        __syncthreads();
        if (it < 7) {
            *(uint4*)&As[a_row0][a_cs0 * 8] = pa0;
            *(uint4*)&As[a_row1][a_cs1 * 8] = pa1;
            *(uint4*)&Bs[b_row0][b_cs0 * 8] = pb0;
            *(uint4*)&Bs[b_row1][b_cs1 * 8] = pb1;
            __syncthreads();
        }
    }

    // epilogue
    const int gid = lane >> 2, tig = lane & 3;
    #pragma unroll
    for (int mt = 0; mt < 4; mt++) {
        #pragma unroll
        for (int hr = 0; hr < 2; hr++) {
            int m = m0 + wm * 64 + mt * 16 + gid + hr * 8;
            float keep = 1.0f;
            if (MODE == 1 || MODE == 3) keep = (seq[m] != 0) ? 1.0f : 0.0f;
            #pragma unroll
            for (int nt = 0; nt < 4; nt++) {
                int n = n0 + wn * 32 + nt * 8 + tig * 2;
                float v0 = acc[mt][nt][hr * 2 + 0];
                float v1 = acc[mt][nt][hr * 2 + 1];
                if (MODE == 2 || MODE == 3) { v0 += bias[n]; v1 += bias[n + 1]; }
                if (MODE == 1 || MODE == 3) {
                    const float2 rv = *(const float2*)(res + m * 256 + n);
                    v0 = (v0 + rv.x) * keep;
                    v1 = (v1 + rv.y) * keep;
                }
                if (MODE == 2) {
                    v0 = fmaxf(v0, 0.f); v1 = fmaxf(v1, 0.f);
                    *(__half2*)(CoutH + m * 256 + n) = __floats2half2_rn(v0, v1);
                } else {
                    *(float2*)(Cout + m * 256 + n) = make_float2(v0, v1);
                    if (MODE == 3)
                        *(__half2*)(CoutH + m * 256 + n) = __floats2half2_rn(v0, v1);
                }
            }
        }
    }
}

// ----------------------------------------------------------------------------
// Cluster-bucketed attention: block per (b,h). Counting sort of tokens by
// cluster id; each thread's query iterates only its own cluster's key list.
// ----------------------------------------------------------------------------
__global__ __launch_bounds__(256, 1) void attn_kernel(const int* __restrict__ seq) {
    extern __shared__ float sm[];
    float* Ks = sm;                    // [256][64]
    float* Vs = sm + Tn * DHn;
    __shared__ int sids[Tn];
    __shared__ int klist[Tn];
    __shared__ int cnt[Kcl], off[Kcl], cur[Kcl];

    const int b = blockIdx.x >> 2;
    const int h = blockIdx.x & 3;
    const int tid = threadIdx.x;

    for (int idx = tid; idx < Tn * DHn; idx += 256) {
        int t = idx >> 6, d = idx & 63;
        int gi = (b * Tn + t) * Cn + h * DHn + d;
        Ks[idx] = g_K[gi];
        Vs[idx] = g_V[gi];
    }
    sids[tid] = g_ids[b * Tn + tid];
    if (tid < Kcl) { cnt[tid] = 0; }
    __syncthreads();
    atomicAdd(&cnt[sids[tid]], 1);
    __syncthreads();
    if (tid == 0) {
        int acc = 0;
        for (int k = 0; k < Kcl; k++) { off[k] = acc; cur[k] = acc; acc += cnt[k]; }
    }
    __syncthreads();
    {
        int c = sids[tid];
        int pos = atomicAdd(&cur[c], 1);
        klist[pos] = tid;
    }
    __syncthreads();

    const int q = klist[tid];
    const int c = sids[q];
    const bool qvalid = (seq[b * Tn + q] != 0);

    float4 qv[16];
    {
        const float4* qp = (const float4*)(g_Q + (b * Tn + q) * Cn + h * DHn);
        #pragma unroll
        for (int j = 0; j < 16; j++) qv[j] = qp[j];
    }

    float m = -1e30f, ssum = 0.f;
    float4 accv[16];
    #pragma unroll
    for (int j = 0; j < 16; j++) accv[j] = make_float4(0.f, 0.f, 0.f, 0.f);

    if (qvalid) {
        const int cbeg = off[c];
        const int cend = cbeg + cnt[c];
        for (int j = cbeg; j < cend; j++) {
            int k = klist[j];
            const float4* kp = (const float4*)&Ks[k * DHn];
            float dot = 0.f;
            #pragma unroll
            for (int jj = 0; jj < 16; jj++) {
                float4 kvv = kp[jj];
                dot += qv[jj].x * kvv.x + qv[jj].y * kvv.y + qv[jj].z * kvv.z + qv[jj].w * kvv.w;
            }
            float s = dot * 0.125f;
            float nm = fmaxf(m, s);
            float cs = __expf(m - nm);
            float p  = __expf(s - nm);
            ssum = ssum * cs + p;
            const float4* vp = (const float4*)&Vs[k * DHn];
            #pragma unroll
            for (int jj = 0; jj < 16; jj++) {
                float4 vv = vp[jj];
                accv[jj].x = accv[jj].x * cs + p * vv.x;
                accv[jj].y = accv[jj].y * cs + p * vv.y;
                accv[jj].z = accv[jj].z * cs + p * vv.z;
                accv[jj].w = accv[jj].w * cs + p * vv.w;
            }
            m = nm;
        }
    }

    float inv = qvalid ? (1.0f / ssum) : 0.0f;
    __half2* op = (__half2*)(g_attnh + (b * Tn + q) * Cn + h * DHn);
    #pragma unroll
    for (int j = 0; j < 16; j++) {
        op[j * 2 + 0] = __floats2half2_rn(accv[j].x * inv, accv[j].y * inv);
        op[j * 2 + 1] = __floats2half2_rn(accv[j].z * inv, accv[j].w * inv);
    }
}

// ----------------------------------------------------------------------------
// Logits
// ----------------------------------------------------------------------------
__global__ __launch_bounds__(256) void logits_kernel(const int* __restrict__ pos_seqs,
                                                     const int* __restrict__ neg_seqs,
                                                     const float* __restrict__ item_emb,
                                                     float* __restrict__ out) {
    int lane = threadIdx.x & 31, warp = threadIdx.x >> 5;
    int i = blockIdx.x * 8 + warp;
    const float* o  = g_out + i * Cn;
    const float* ul = g_ulat + (i >> 8) * USER_H;
    const float* pe = item_emb + pos_seqs[i] * ITEM_H;
    const float* ne = item_emb + neg_seqs[i] * ITEM_H;
    float sp = 0.f, sn = 0.f;
    for (int c = lane; c < ITEM_H; c += 32) {
        float ov = o[c];
        sp += ov * pe[c];
        sn += ov * ne[c];
    }
    for (int j = lane; j < USER_H; j += 32) {
        float ov = o[ITEM_H + j];
        float u  = ul[j];
        sp += ov * u;
        sn += ov * u;
    }
    sp = warp_sum(sp);
    sn = warp_sum(sn);
    if (lane == 0) {
        out[i]        = sp;
        out[NTOK + i] = sn;
    }
}

// ----------------------------------------------------------------------------
// Launch
// ----------------------------------------------------------------------------
extern "C" void kernel_launch(void* const* d_in, const int* in_sizes, int n_in,
                              void* d_out, int out_size) {
    const int*   uid      = (const int*)d_in[0];
    const int*   seq      = (const int*)d_in[1];
    const int*   pos_seqs = (const int*)d_in[2];
    const int*   neg_seqs = (const int*)d_in[3];
    const float* item_emb = (const float*)d_in[4];
    const float* user_emb = (const float*)d_in[5];
    const float* pos_emb  = (const float*)d_in[6];
    const float* Wq = (const float*)d_in[7];
    const float* Wk = (const float*)d_in[8];
    const float* Wv = (const float*)d_in[9];
    const float* Wo = (const float*)d_in[10];
    const float* ln1g = (const float*)d_in[11];
    const float* ln1b = (const float*)d_in[12];
    const float* ln2g = (const float*)d_in[13];
    const float* ln2b = (const float*)d_in[14];
    const float* W1 = (const float*)d_in[15];
    const float* b1 = (const float*)d_in[16];
    const float* W2 = (const float*)d_in[17];
    const float* b2 = (const float*)d_in[18];
    const float* lnfg = (const float*)d_in[19];
    const float* lnfb = (const float*)d_in[20];
    float* out = (float*)d_out;

    float *px, *pqin, *pQ, *pK, *pV, *pout;
    __half *pxh, *pqinh, *pattnh, *ph1h, *pwh;
    cudaGetSymbolAddress((void**)&px,     g_x);
    cudaGetSymbolAddress((void**)&pqin,   g_qin);
    cudaGetSymbolAddress((void**)&pQ,     g_Q);
    cudaGetSymbolAddress((void**)&pK,     g_K);
    cudaGetSymbolAddress((void**)&pV,     g_V);
    cudaGetSymbolAddress((void**)&pout,   g_out);
    cudaGetSymbolAddress((void**)&pxh,    g_xh);
    cudaGetSymbolAddress((void**)&pqinh,  g_qinh);
    cudaGetSymbolAddress((void**)&pattnh, g_attnh);
    cudaGetSymbolAddress((void**)&ph1h,   g_h1h);
    cudaGetSymbolAddress((void**)&pwh,    g_Wh);

    const int WSZ = Cn * Cn;
    const int ASZ = Ln * WSZ;

    const int attn_smem = 2 * Tn * DHn * (int)sizeof(float);  // 128 KB
    cudaFuncSetAttribute(attn_kernel, cudaFuncAttributeMaxDynamicSharedMemorySize, attn_smem);

    embed_kernel<<<NC / 256, 256>>>(uid, seq, item_emb, user_emb, pos_emb);   // 0
    convw_kernel<<<(6 * ASZ) / 256, 256>>>(Wq, Wk, Wv, Wo, W1, W2);           // 1
    kmeans_kernel<<<Bn, 256>>>();                                             // 2
    mask_kernel<<<NC / 256, 256>>>(seq);                                      // 3

    const dim3 ggrid(Cn / 128, NTOK / 128);

    for (int l = 0; l < Ln; l++) {
        const __half* whq = pwh + 0 * ASZ + l * WSZ;
        const __half* whk = pwh + 1 * ASZ + l * WSZ;
        const __half* whv = pwh + 2 * ASZ + l * WSZ;
        const __half* who = pwh + 3 * ASZ + l * WSZ;
        const __half* wh1 = pwh + 4 * ASZ + l * WSZ;
        const __half* wh2 = pwh + 5 * ASZ + l * WSZ;

        ln_kernel<<<NTOK / 8, 256>>>(px, pqin, pqinh, ln1g + l * Cn, ln1b + l * Cn);  // 4
        hgemm_kernel<0><<<ggrid, 256>>>(pqinh, whq, pQ, nullptr, nullptr, nullptr, nullptr);  // 5
        hgemm_kernel<0><<<ggrid, 256>>>(pxh,   whk, pK, nullptr, nullptr, nullptr, nullptr);
        hgemm_kernel<0><<<ggrid, 256>>>(pxh,   whv, pV, nullptr, nullptr, nullptr, nullptr);
        attn_kernel<<<Bn * Hn, 256, attn_smem>>>(seq);
        hgemm_kernel<1><<<ggrid, 256>>>(pattnh, who, px, nullptr, pqin, nullptr, seq);
        ln_kernel<<<NTOK / 8, 256>>>(px, pqin, pqinh, ln2g + l * Cn, ln2b + l * Cn);
        hgemm_kernel<2><<<ggrid, 256>>>(pqinh, wh1, nullptr, ph1h, nullptr, b1 + l * Cn, nullptr);
        hgemm_kernel<3><<<ggrid, 256>>>(ph1h, wh2, px, pxh, px, b2 + l * Cn, seq);
    }

    ln_kernel<<<NTOK / 8, 256>>>(px, pout, ph1h, lnfg, lnfb);

    ulat_kernel<<<Bn, USER_H>>>(uid, user_emb);
    logits_kernel<<<NTOK / 8, 256>>>(pos_seqs, neg_seqs, item_emb, out);
}

// round 5
// speedup vs baseline: 2.5443x; 1.1883x over previous
#include <cuda_runtime.h>
#include <cuda_fp16.h>
#include <stdint.h>
#include <math.h>

// ----------------------------------------------------------------------------
// UPTRec forward. Round 5 (= round 4 + restored Hn constant):
// cp.async double-buffered fp16 GEMMs, fp16 Q/K/V, mask fused into k-means,
// final LN fused into logits.
// ----------------------------------------------------------------------------

constexpr int Bn   = 512;
constexpr int Tn   = 256;
constexpr int Cn   = 256;
constexpr int Hn   = 4;
constexpr int DHn  = 64;
constexpr int Ln   = 2;
constexpr int Kcl  = 16;
constexpr int ITEM_H = 192;
constexpr int USER_H = 64;
constexpr int NTOK = Bn * Tn;          // 131072
constexpr int NC   = NTOK * Cn;        // 33,554,432

// fp32 scratch
__device__ float g_x[NC];
__device__ float g_qin[NC];
__device__ int   g_ids[NTOK];
// fp16 buffers
__device__ __align__(16) __half g_xh[NC];
__device__ __align__(16) __half g_qinh[NC];
__device__ __align__(16) __half g_attnh[NC];
__device__ __align__(16) __half g_h1h[NC];
__device__ __align__(16) __half g_Qh[NC];
__device__ __align__(16) __half g_Kh[NC];
__device__ __align__(16) __half g_Vh[NC];
// fp16 weights: [6 arrays][L][C][C] order q,k,v,o,W1,W2
__device__ __align__(16) __half g_Wh[6 * Ln * Cn * Cn];

// ----------------------------------------------------------------------------
__device__ __forceinline__ float warp_sum(float v) {
    v += __shfl_xor_sync(0xffffffffu, v, 16);
    v += __shfl_xor_sync(0xffffffffu, v, 8);
    v += __shfl_xor_sync(0xffffffffu, v, 4);
    v += __shfl_xor_sync(0xffffffffu, v, 2);
    v += __shfl_xor_sync(0xffffffffu, v, 1);
    return v;
}

__device__ __forceinline__ void cp_async16(uint32_t saddr, const void* gptr) {
    asm volatile("cp.async.cg.shared.global [%0], [%1], 16;\n" :: "r"(saddr), "l"(gptr));
}
__device__ __forceinline__ void cp_commit() {
    asm volatile("cp.async.commit_group;\n");
}
template <int N>
__device__ __forceinline__ void cp_wait() {
    asm volatile("cp.async.wait_group %0;\n" :: "n"(N));
}

// ----------------------------------------------------------------------------
// Embedding (unmasked x for k-means)
// ----------------------------------------------------------------------------
__global__ void embed_kernel(const int* __restrict__ uid,
                             const int* __restrict__ seq,
                             const float* __restrict__ item_emb,
                             const float* __restrict__ user_emb,
                             const float* __restrict__ pos_emb) {
    int idx = blockIdx.x * blockDim.x + threadIdx.x;
    if (idx >= NC) return;
    int i = idx >> 8;
    int c = idx & 255;
    int b = i >> 8;
    int t = i & 255;
    float v;
    if (c < ITEM_H) v = item_emb[seq[i] * ITEM_H + c];
    else            v = user_emb[uid[b] * USER_H + (c - ITEM_H)];
    g_x[idx] = v + pos_emb[t * Cn + c];
}

// fp32 -> fp16 weight conversion
__global__ void convw_kernel(const float* __restrict__ Wq, const float* __restrict__ Wk,
                             const float* __restrict__ Wv, const float* __restrict__ Wo,
                             const float* __restrict__ W1, const float* __restrict__ W2) {
    int idx = blockIdx.x * blockDim.x + threadIdx.x;
    const int per = Ln * Cn * Cn;
    if (idx >= 6 * per) return;
    int a = idx / per;
    int r = idx - a * per;
    const float* s;
    switch (a) {
        case 0: s = Wq; break; case 1: s = Wk; break; case 2: s = Wv; break;
        case 3: s = Wo; break; case 4: s = W1; break; default: s = W2; break;
    }
    g_Wh[idx] = __float2half(s[r]);
}

// ----------------------------------------------------------------------------
// Batched Lloyd k-means (exact fp32) + fused pad-mask epilogue
// ----------------------------------------------------------------------------
__global__ __launch_bounds__(256) void kmeans_kernel(const int* __restrict__ seq) {
    __shared__ float cent[Kcl * Cn];
    __shared__ float xsq[Tn];
    __shared__ float csq[Kcl];
    __shared__ int   sids[Tn];
    __shared__ int   cnt[Kcl];

    const int b    = blockIdx.x;
    const int tid  = threadIdx.x;
    const int lane = tid & 31;
    const int warp = tid >> 5;
    float* Xb = g_x + b * Tn * Cn;

    for (int i = tid; i < Kcl * Cn; i += 256) cent[i] = Xb[i];

    for (int r = 0; r < 32; r++) {
        int t = warp * 32 + r;
        float s = 0.f;
        #pragma unroll
        for (int j = 0; j < 8; j++) {
            float xv = Xb[t * Cn + lane + 32 * j];
            s += xv * xv;
        }
        s = warp_sum(s);
        if (lane == 0) xsq[t] = s;
    }
    __syncthreads();

    for (int iter = 0; iter <= 10; iter++) {
        if (tid < Kcl) {
            float s = 0.f;
            for (int c = 0; c < Cn; c++) { float v = cent[tid * Cn + c]; s += v * v; }
            csq[tid] = s;
        }
        __syncthreads();

        for (int r = 0; r < 32; r++) {
            int t = warp * 32 + r;
            float xv[8];
            #pragma unroll
            for (int j = 0; j < 8; j++) xv[j] = Xb[t * Cn + lane + 32 * j];
            float best = 3.4e38f; int bi = 0;
            #pragma unroll
            for (int k = 0; k < Kcl; k++) {
                float p = 0.f;
                #pragma unroll
                for (int j = 0; j < 8; j++) p += xv[j] * cent[k * Cn + lane + 32 * j];
                p = warp_sum(p);
                float d = xsq[t] - 2.0f * p + csq[k];
                if (d < best) { best = d; bi = k; }
            }
            if (lane == 0) sids[t] = bi;
        }
        __syncthreads();

        if (iter == 10) break;

        if (tid < Kcl) cnt[tid] = 0;
        __syncthreads();
        atomicAdd(&cnt[sids[tid]], 1);
        __syncthreads();

        {
            const int c = tid;
            float acc[Kcl];
            #pragma unroll
            for (int k = 0; k < Kcl; k++) acc[k] = 0.f;
            for (int t = 0; t < Tn; t++) {
                float v = Xb[t * Cn + c];
                int id = sids[t];
                #pragma unroll
                for (int k = 0; k < Kcl; k++) acc[k] += (id == k) ? v : 0.f;
            }
            __syncthreads();
            #pragma unroll
            for (int k = 0; k < Kcl; k++) {
                if (cnt[k] > 0) cent[k * Cn + c] = acc[k] / fmaxf((float)cnt[k], 1.0f);
            }
        }
        __syncthreads();
    }

    g_ids[b * Tn + tid] = sids[tid];

    // fused pad-mask: overwrite this batch's x with masked values + fp16 mirror
    __syncthreads();
    __half* Xh = g_xh + b * Tn * Cn;
    for (int idx = tid; idx < Tn * Cn; idx += 256) {
        int t = idx >> 8;
        float v = Xb[idx];
        if (seq[b * Tn + t] == 0) v = 0.0f;
        Xb[idx] = v;
        Xh[idx] = __float2half(v);
    }
}

// ----------------------------------------------------------------------------
// LayerNorm: warp per row; WF32 controls fp32 store
// ----------------------------------------------------------------------------
template <bool WF32>
__global__ __launch_bounds__(256) void ln_kernel(const float* __restrict__ in,
                                                 float* __restrict__ out,
                                                 __half* __restrict__ outh,
                                                 const float* __restrict__ g,
                                                 const float* __restrict__ bb) {
    int lane = threadIdx.x & 31, warp = threadIdx.x >> 5;
    int row = blockIdx.x * 8 + warp;
    const float* r = in + row * Cn;
    float v[8];
    #pragma unroll
    for (int j = 0; j < 8; j++) v[j] = r[lane + 32 * j];
    float s = 0.f;
    #pragma unroll
    for (int j = 0; j < 8; j++) s += v[j];
    s = warp_sum(s);
    float mu = s * (1.0f / 256.0f);
    float q = 0.f;
    #pragma unroll
    for (int j = 0; j < 8; j++) { float d = v[j] - mu; q += d * d; }
    q = warp_sum(q);
    float rinv = rsqrtf(q * (1.0f / 256.0f) + 1e-8f);
    #pragma unroll
    for (int j = 0; j < 8; j++) {
        int c = lane + 32 * j;
        float o = g[c] * (v[j] - mu) * rinv + bb[c];
        if (WF32) out[row * Cn + c] = o;
        outh[row * Cn + c] = __float2half(o);
    }
}

// ----------------------------------------------------------------------------
// fp16 tensor-core GEMM with cp.async double buffering.
// C[M=131072, N=256] = A @ W, K=256. BM=128, BN=128, BK=32, 256 threads.
// MODE 0: half out = acc                  (Q/K/V projections)
// MODE 1: fp32 out = (acc + res) * keep   (post-attention x)
// MODE 2: half out = relu(acc + bias)     (FFN hidden)
// MODE 3: fp32+half out = (acc+bias+res)*keep
// ----------------------------------------------------------------------------
__device__ __forceinline__ void ldsm4(uint32_t* r, uint32_t addr) {
    asm volatile("ldmatrix.sync.aligned.m8n8.x4.shared.b16 {%0,%1,%2,%3}, [%4];"
        : "=r"(r[0]), "=r"(r[1]), "=r"(r[2]), "=r"(r[3]) : "r"(addr));
}
__device__ __forceinline__ void ldsm4t(uint32_t* r, uint32_t addr) {
    asm volatile("ldmatrix.sync.aligned.m8n8.x4.trans.shared.b16 {%0,%1,%2,%3}, [%4];"
        : "=r"(r[0]), "=r"(r[1]), "=r"(r[2]), "=r"(r[3]) : "r"(addr));
}
__device__ __forceinline__ void mma16816(float* c, const uint32_t* a, const uint32_t* b) {
    asm volatile("mma.sync.aligned.m16n8k16.row.col.f32.f16.f16.f32 "
        "{%0,%1,%2,%3}, {%4,%5,%6,%7}, {%8,%9}, {%0,%1,%2,%3};"
        : "+f"(c[0]), "+f"(c[1]), "+f"(c[2]), "+f"(c[3])
        : "r"(a[0]), "r"(a[1]), "r"(a[2]), "r"(a[3]), "r"(b[0]), "r"(b[1]));
}

constexpr int BKg  = 32;
constexpr int APAD = 8;    // As row = 40 halves
constexpr int BPAD = 8;    // Bs row = 136 halves

template <int MODE>
__global__ __launch_bounds__(256, 2) void hgemm_kernel(const __half* __restrict__ A,
                                                       const __half* __restrict__ W,
                                                       float* __restrict__ Cout,
                                                       __half* __restrict__ CoutH,
                                                       const float* __restrict__ res,
                                                       const float* __restrict__ bias,
                                                       const int* __restrict__ seq) {
    __shared__ __half As[2][128][BKg + APAD];
    __shared__ __half Bs[2][BKg][128 + BPAD];

    const int tid  = threadIdx.x;
    const int lane = tid & 31;
    const int warp = tid >> 5;
    const int wm   = warp >> 2;          // 0..1
    const int wn   = warp & 3;           // 0..3
    const int m0   = blockIdx.y * 128;
    const int n0   = blockIdx.x * 128;

    float acc[4][4][4];
    #pragma unroll
    for (int i = 0; i < 4; i++)
        #pragma unroll
        for (int j = 0; j < 4; j++)
            #pragma unroll
            for (int v = 0; v < 4; v++) acc[i][j][v] = 0.f;

    const int a_row0 = tid >> 2,          a_c0 = (tid & 3) * 8;
    const int a_row1 = (tid + 256) >> 2,  a_c1 = ((tid + 256) & 3) * 8;
    const int b_row0 = tid >> 4,          b_c0 = (tid & 15) * 8;
    const int b_row1 = (tid + 256) >> 4,  b_c1 = ((tid + 256) & 15) * 8;

    auto load_stage = [&](int buf, int k0) {
        cp_async16((uint32_t)__cvta_generic_to_shared(&As[buf][a_row0][a_c0]),
                   A + (m0 + a_row0) * 256 + k0 + a_c0);
        cp_async16((uint32_t)__cvta_generic_to_shared(&As[buf][a_row1][a_c1]),
                   A + (m0 + a_row1) * 256 + k0 + a_c1);
        cp_async16((uint32_t)__cvta_generic_to_shared(&Bs[buf][b_row0][b_c0]),
                   W + (k0 + b_row0) * 256 + n0 + b_c0);
        cp_async16((uint32_t)__cvta_generic_to_shared(&Bs[buf][b_row1][b_c1]),
                   W + (k0 + b_row1) * 256 + n0 + b_c1);
        cp_commit();
    };

    load_stage(0, 0);

    for (int it = 0; it < 8; it++) {
        const int buf = it & 1;
        if (it < 7) load_stage(buf ^ 1, (it + 1) * BKg);
        if (it < 7) cp_wait<1>(); else cp_wait<0>();
        __syncthreads();

        uint32_t as_base = (uint32_t)__cvta_generic_to_shared(&As[buf][0][0]);
        uint32_t bs_base = (uint32_t)__cvta_generic_to_shared(&Bs[buf][0][0]);

        #pragma unroll
        for (int kk = 0; kk < BKg; kk += 16) {
            uint32_t aF[4][4];
            uint32_t bF[4][2];
            #pragma unroll
            for (int mt = 0; mt < 4; mt++) {
                int row = wm * 64 + mt * 16 + (lane & 15);
                int col = kk + (lane >> 4) * 8;
                ldsm4(aF[mt], as_base + (uint32_t)((row * (BKg + APAD) + col) * 2));
            }
            #pragma unroll
            for (int np = 0; np < 2; np++) {
                int k = kk + (lane & 15);
                int n = wn * 32 + np * 16 + (lane >> 4) * 8;
                uint32_t r[4];
                ldsm4t(r, bs_base + (uint32_t)((k * (128 + BPAD) + n) * 2));
                bF[np * 2][0] = r[0]; bF[np * 2][1] = r[1];
                bF[np * 2 + 1][0] = r[2]; bF[np * 2 + 1][1] = r[3];
            }
            #pragma unroll
            for (int mt = 0; mt < 4; mt++)
                #pragma unroll
                for (int nt = 0; nt < 4; nt++)
                    mma16816(acc[mt][nt], aF[mt], bF[nt]);
        }
        __syncthreads();
    }

    // epilogue
    const int gid = lane >> 2, tig = lane & 3;
    #pragma unroll
    for (int mt = 0; mt < 4; mt++) {
        #pragma unroll
        for (int hr = 0; hr < 2; hr++) {
            int m = m0 + wm * 64 + mt * 16 + gid + hr * 8;
            float keep = 1.0f;
            if (MODE == 1 || MODE == 3) keep = (seq[m] != 0) ? 1.0f : 0.0f;
            #pragma unroll
            for (int nt = 0; nt < 4; nt++) {
                int n = n0 + wn * 32 + nt * 8 + tig * 2;
                float v0 = acc[mt][nt][hr * 2 + 0];
                float v1 = acc[mt][nt][hr * 2 + 1];
                if (MODE == 2 || MODE == 3) { v0 += bias[n]; v1 += bias[n + 1]; }
                if (MODE == 1 || MODE == 3) {
                    const float2 rv = *(const float2*)(res + m * 256 + n);
                    v0 = (v0 + rv.x) * keep;
                    v1 = (v1 + rv.y) * keep;
                }
                if (MODE == 2) { v0 = fmaxf(v0, 0.f); v1 = fmaxf(v1, 0.f); }
                if (MODE == 0 || MODE == 2) {
                    *(__half2*)(CoutH + m * 256 + n) = __floats2half2_rn(v0, v1);
                } else {
                    *(float2*)(Cout + m * 256 + n) = make_float2(v0, v1);
                    if (MODE == 3)
                        *(__half2*)(CoutH + m * 256 + n) = __floats2half2_rn(v0, v1);
                }
            }
        }
    }
}

// ----------------------------------------------------------------------------
// Cluster-bucketed attention. fp16 Q/K/V in gmem; fp32 smem K/V; fp32 math.
// ----------------------------------------------------------------------------
__global__ __launch_bounds__(256, 1) void attn_kernel(const int* __restrict__ seq) {
    extern __shared__ float sm[];
    float* Ks = sm;                    // [256][64]
    float* Vs = sm + Tn * DHn;
    __shared__ int sids[Tn];
    __shared__ int klist[Tn];
    __shared__ int cnt[Kcl], off[Kcl], cur[Kcl];

    const int b = blockIdx.x >> 2;     // Hn = 4
    const int h = blockIdx.x & 3;
    const int tid = threadIdx.x;

    const __half2* Kg = (const __half2*)g_Kh;
    const __half2* Vg = (const __half2*)g_Vh;
    for (int idx = tid; idx < Tn * 32; idx += 256) {
        int t = idx >> 5, d2 = idx & 31;
        int gi2 = ((b * Tn + t) * Cn + h * DHn) / 2 + d2;
        float2 kf = __half22float2(Kg[gi2]);
        float2 vf = __half22float2(Vg[gi2]);
        Ks[t * DHn + d2 * 2]     = kf.x;
        Ks[t * DHn + d2 * 2 + 1] = kf.y;
        Vs[t * DHn + d2 * 2]     = vf.x;
        Vs[t * DHn + d2 * 2 + 1] = vf.y;
    }
    sids[tid] = g_ids[b * Tn + tid];
    if (tid < Kcl) cnt[tid] = 0;
    __syncthreads();
    atomicAdd(&cnt[sids[tid]], 1);
    __syncthreads();
    if (tid == 0) {
        int acc = 0;
        for (int k = 0; k < Kcl; k++) { off[k] = acc; cur[k] = acc; acc += cnt[k]; }
    }
    __syncthreads();
    {
        int c = sids[tid];
        int pos = atomicAdd(&cur[c], 1);
        klist[pos] = tid;
    }
    __syncthreads();

    const int q = klist[tid];
    const int c = sids[q];
    const bool qvalid = (seq[b * Tn + q] != 0);

    float4 qv[16];
    {
        const __half2* qp = (const __half2*)(g_Qh + (b * Tn + q) * Cn + h * DHn);
        #pragma unroll
        for (int j = 0; j < 16; j++) {
            float2 f0 = __half22float2(qp[j * 2]);
            float2 f1 = __half22float2(qp[j * 2 + 1]);
            qv[j] = make_float4(f0.x, f0.y, f1.x, f1.y);
        }
    }

    float m = -1e30f, ssum = 0.f;
    float4 accv[16];
    #pragma unroll
    for (int j = 0; j < 16; j++) accv[j] = make_float4(0.f, 0.f, 0.f, 0.f);

    if (qvalid) {
        const int cbeg = off[c];
        const int cend = cbeg + cnt[c];
        for (int j = cbeg; j < cend; j++) {
            int k = klist[j];
            const float4* kp = (const float4*)&Ks[k * DHn];
            float dot = 0.f;
            #pragma unroll
            for (int jj = 0; jj < 16; jj++) {
                float4 kvv = kp[jj];
                dot += qv[jj].x * kvv.x + qv[jj].y * kvv.y + qv[jj].z * kvv.z + qv[jj].w * kvv.w;
            }
            float s = dot * 0.125f;
            float nm = fmaxf(m, s);
            float cs = __expf(m - nm);
            float p  = __expf(s - nm);
            ssum = ssum * cs + p;
            const float4* vp = (const float4*)&Vs[k * DHn];
            #pragma unroll
            for (int jj = 0; jj < 16; jj++) {
                float4 vv = vp[jj];
                accv[jj].x = accv[jj].x * cs + p * vv.x;
                accv[jj].y = accv[jj].y * cs + p * vv.y;
                accv[jj].z = accv[jj].z * cs + p * vv.z;
                accv[jj].w = accv[jj].w * cs + p * vv.w;
            }
            m = nm;
        }
    }

    float inv = qvalid ? (1.0f / ssum) : 0.0f;
    __half2* op = (__half2*)(g_attnh + (b * Tn + q) * Cn + h * DHn);
    #pragma unroll
    for (int j = 0; j < 16; j++) {
        op[j * 2 + 0] = __floats2half2_rn(accv[j].x * inv, accv[j].y * inv);
        op[j * 2 + 1] = __floats2half2_rn(accv[j].z * inv, accv[j].w * inv);
    }
}

// ----------------------------------------------------------------------------
// Fused final LayerNorm + logits: warp per token row
// ----------------------------------------------------------------------------
__global__ __launch_bounds__(256) void lnlogits_kernel(const int* __restrict__ uid,
                                                       const int* __restrict__ pos_seqs,
                                                       const int* __restrict__ neg_seqs,
                                                       const float* __restrict__ item_emb,
                                                       const float* __restrict__ user_emb,
                                                       const float* __restrict__ lnfg,
                                                       const float* __restrict__ lnfb,
                                                       float* __restrict__ out) {
    int lane = threadIdx.x & 31, warp = threadIdx.x >> 5;
    int i = blockIdx.x * 8 + warp;
    int b = i >> 8;
    const float* r = g_x + i * Cn;
    float v[8];
    #pragma unroll
    for (int j = 0; j < 8; j++) v[j] = r[lane + 32 * j];
    float s = 0.f;
    #pragma unroll
    for (int j = 0; j < 8; j++) s += v[j];
    s = warp_sum(s);
    float mu = s * (1.0f / 256.0f);
    float q = 0.f;
    #pragma unroll
    for (int j = 0; j < 8; j++) { float d = v[j] - mu; q += d * d; }
    q = warp_sum(q);
    float rinv = rsqrtf(q * (1.0f / 256.0f) + 1e-8f);

    const float* pe = item_emb + pos_seqs[i] * ITEM_H;
    const float* ne = item_emb + neg_seqs[i] * ITEM_H;
    const float* ul = user_emb + uid[b] * USER_H;

    float sp = 0.f, sn = 0.f;
    #pragma unroll
    for (int j = 0; j < 8; j++) {
        int c = lane + 32 * j;
        float o = lnfg[c] * (v[j] - mu) * rinv + lnfb[c];
        if (c < ITEM_H) {
            sp += o * pe[c];
            sn += o * ne[c];
        } else {
            float u = ul[c - ITEM_H];
            sp += o * u;
            sn += o * u;
        }
    }
    sp = warp_sum(sp);
    sn = warp_sum(sn);
    if (lane == 0) {
        out[i]        = sp;
        out[NTOK + i] = sn;
    }
}

// ----------------------------------------------------------------------------
// Launch
// ----------------------------------------------------------------------------
extern "C" void kernel_launch(void* const* d_in, const int* in_sizes, int n_in,
                              void* d_out, int out_size) {
    const int*   uid      = (const int*)d_in[0];
    const int*   seq      = (const int*)d_in[1];
    const int*   pos_seqs = (const int*)d_in[2];
    const int*   neg_seqs = (const int*)d_in[3];
    const float* item_emb = (const float*)d_in[4];
    const float* user_emb = (const float*)d_in[5];
    const float* pos_emb  = (const float*)d_in[6];
    const float* Wq = (const float*)d_in[7];
    const float* Wk = (const float*)d_in[8];
    const float* Wv = (const float*)d_in[9];
    const float* Wo = (const float*)d_in[10];
    const float* ln1g = (const float*)d_in[11];
    const float* ln1b = (const float*)d_in[12];
    const float* ln2g = (const float*)d_in[13];
    const float* ln2b = (const float*)d_in[14];
    const float* W1 = (const float*)d_in[15];
    const float* b1 = (const float*)d_in[16];
    const float* W2 = (const float*)d_in[17];
    const float* b2 = (const float*)d_in[18];
    const float* lnfg = (const float*)d_in[19];
    const float* lnfb = (const float*)d_in[20];
    float* out = (float*)d_out;

    float *px, *pqin;
    __half *pxh, *pqinh, *pattnh, *ph1h, *pwh, *pQh, *pKh, *pVh;
    cudaGetSymbolAddress((void**)&px,     g_x);
    cudaGetSymbolAddress((void**)&pqin,   g_qin);
    cudaGetSymbolAddress((void**)&pxh,    g_xh);
    cudaGetSymbolAddress((void**)&pqinh,  g_qinh);
    cudaGetSymbolAddress((void**)&pattnh, g_attnh);
    cudaGetSymbolAddress((void**)&ph1h,   g_h1h);
    cudaGetSymbolAddress((void**)&pwh,    g_Wh);
    cudaGetSymbolAddress((void**)&pQh,    g_Qh);
    cudaGetSymbolAddress((void**)&pKh,    g_Kh);
    cudaGetSymbolAddress((void**)&pVh,    g_Vh);

    const int WSZ = Cn * Cn;
    const int ASZ = Ln * WSZ;

    const int attn_smem = 2 * Tn * DHn * (int)sizeof(float);  // 128 KB
    cudaFuncSetAttribute(attn_kernel, cudaFuncAttributeMaxDynamicSharedMemorySize, attn_smem);

    const dim3 ggrid(Cn / 128, NTOK / 128);

    embed_kernel<<<NC / 256, 256>>>(uid, seq, item_emb, user_emb, pos_emb);   // 0
    convw_kernel<<<(6 * ASZ) / 256, 256>>>(Wq, Wk, Wv, Wo, W1, W2);           // 1
    kmeans_kernel<<<Bn, 256>>>(seq);                                          // 2 (+mask)

    for (int l = 0; l < Ln; l++) {
        const __half* whq = pwh + 0 * ASZ + l * WSZ;
        const __half* whk = pwh + 1 * ASZ + l * WSZ;
        const __half* whv = pwh + 2 * ASZ + l * WSZ;
        const __half* who = pwh + 3 * ASZ + l * WSZ;
        const __half* wh1 = pwh + 4 * ASZ + l * WSZ;
        const __half* wh2 = pwh + 5 * ASZ + l * WSZ;

        // K, V projections (A = masked x fp16); index 3 = profiled HGEMM
        hgemm_kernel<0><<<ggrid, 256>>>(pxh, whk, nullptr, pKh, nullptr, nullptr, nullptr);
        hgemm_kernel<0><<<ggrid, 256>>>(pxh, whv, nullptr, pVh, nullptr, nullptr, nullptr);
        // q_in = LN1(x): fp32 (residual) + fp16
        ln_kernel<true><<<NTOK / 8, 256>>>(px, pqin, pqinh, ln1g + l * Cn, ln1b + l * Cn);
        hgemm_kernel<0><<<ggrid, 256>>>(pqinh, whq, nullptr, pQh, nullptr, nullptr, nullptr);
        // bucketed attention
        attn_kernel<<<Bn * Hn, 256, attn_smem>>>(seq);
        // x = (q_in + attn @ Wo) * keep
        hgemm_kernel<1><<<ggrid, 256>>>(pattnh, who, px, nullptr, pqin, nullptr, seq);
        // f = LN2(x): fp16 only
        ln_kernel<false><<<NTOK / 8, 256>>>(px, nullptr, pqinh, ln2g + l * Cn, ln2b + l * Cn);
        // h1 = relu(f @ W1 + b1)
        hgemm_kernel<2><<<ggrid, 256>>>(pqinh, wh1, nullptr, ph1h, nullptr, b1 + l * Cn, nullptr);
        // x = (x + h1 @ W2 + b2) * keep
        hgemm_kernel<3><<<ggrid, 256>>>(ph1h, wh2, px, pxh, px, b2 + l * Cn, seq);
    }

    // fused final LN + logits
    lnlogits_kernel<<<NTOK / 8, 256>>>(uid, pos_seqs, neg_seqs, item_emb, user_emb,
                                       lnfg, lnfb, out);
}

// round 6
// speedup vs baseline: 2.5648x; 1.0081x over previous
#include <cuda_runtime.h>
#include <cuda_fp16.h>
#include <stdint.h>
#include <math.h>

// ----------------------------------------------------------------------------
// UPTRec forward. Round 6: 3-stage cp.async HGEMM (1 sync/iter), fused K+V
// projection GEMM (N=512), dynamic smem, kmeans placed at profiled slot.
// ----------------------------------------------------------------------------

constexpr int Bn   = 512;
constexpr int Tn   = 256;
constexpr int Cn   = 256;
constexpr int Hn   = 4;
constexpr int DHn  = 64;
constexpr int Ln   = 2;
constexpr int Kcl  = 16;
constexpr int ITEM_H = 192;
constexpr int USER_H = 64;
constexpr int NTOK = Bn * Tn;          // 131072
constexpr int NC   = NTOK * Cn;        // 33,554,432

// fp32 scratch
__device__ float g_x[NC];
__device__ float g_qin[NC];
__device__ int   g_ids[NTOK];
// fp16 buffers
__device__ __align__(16) __half g_xh[NC];
__device__ __align__(16) __half g_qinh[NC];
__device__ __align__(16) __half g_attnh[NC];
__device__ __align__(16) __half g_h1h[NC];
__device__ __align__(16) __half g_Qh[NC];
__device__ __align__(16) __half g_Kh[NC];
__device__ __align__(16) __half g_Vh[NC];
// fp16 weights: [4 arrays][L][C][C] order q,o,W1,W2
__device__ __align__(16) __half g_Wh[4 * Ln * Cn * Cn];
// fused KV weights: [L][C][2C]  (cols 0..255 = Wk, 256..511 = Wv)
__device__ __align__(16) __half g_Wkvh[Ln * Cn * 2 * Cn];

// ----------------------------------------------------------------------------
__device__ __forceinline__ float warp_sum(float v) {
    v += __shfl_xor_sync(0xffffffffu, v, 16);
    v += __shfl_xor_sync(0xffffffffu, v, 8);
    v += __shfl_xor_sync(0xffffffffu, v, 4);
    v += __shfl_xor_sync(0xffffffffu, v, 2);
    v += __shfl_xor_sync(0xffffffffu, v, 1);
    return v;
}

__device__ __forceinline__ void cp_async16(uint32_t saddr, const void* gptr) {
    asm volatile("cp.async.cg.shared.global [%0], [%1], 16;\n" :: "r"(saddr), "l"(gptr));
}
__device__ __forceinline__ void cp_commit() {
    asm volatile("cp.async.commit_group;\n");
}
template <int N>
__device__ __forceinline__ void cp_wait() {
    asm volatile("cp.async.wait_group %0;\n" :: "n"(N));
}

// ----------------------------------------------------------------------------
// Embedding (unmasked x for k-means)
// ----------------------------------------------------------------------------
__global__ void embed_kernel(const int* __restrict__ uid,
                             const int* __restrict__ seq,
                             const float* __restrict__ item_emb,
                             const float* __restrict__ user_emb,
                             const float* __restrict__ pos_emb) {
    int idx = blockIdx.x * blockDim.x + threadIdx.x;
    if (idx >= NC) return;
    int i = idx >> 8;
    int c = idx & 255;
    int b = i >> 8;
    int t = i & 255;
    float v;
    if (c < ITEM_H) v = item_emb[seq[i] * ITEM_H + c];
    else            v = user_emb[uid[b] * USER_H + (c - ITEM_H)];
    g_x[idx] = v + pos_emb[t * Cn + c];
}

// fp32 -> fp16 weight conversion (q,o,W1,W2)
__global__ void convw_kernel(const float* __restrict__ Wq, const float* __restrict__ Wo,
                             const float* __restrict__ W1, const float* __restrict__ W2) {
    int idx = blockIdx.x * blockDim.x + threadIdx.x;
    const int per = Ln * Cn * Cn;
    if (idx >= 4 * per) return;
    int a = idx / per;
    int r = idx - a * per;
    const float* s;
    switch (a) {
        case 0: s = Wq; break; case 1: s = Wo; break;
        case 2: s = W1; break; default: s = W2; break;
    }
    g_Wh[idx] = __float2half(s[r]);
}

// fused KV weight: [L][k][0:256]=Wk, [256:512]=Wv
__global__ void convkv_kernel(const float* __restrict__ Wk, const float* __restrict__ Wv) {
    int idx = blockIdx.x * blockDim.x + threadIdx.x;
    if (idx >= Ln * Cn * 2 * Cn) return;
    int l = idx / (Cn * 2 * Cn);
    int r = idx - l * (Cn * 2 * Cn);
    int k = r / (2 * Cn);
    int n = r - k * (2 * Cn);
    float v = (n < Cn) ? Wk[(l * Cn + k) * Cn + n] : Wv[(l * Cn + k) * Cn + (n - Cn)];
    g_Wkvh[idx] = __float2half(v);
}

// ----------------------------------------------------------------------------
// Batched Lloyd k-means (exact fp32) + fused pad-mask epilogue
// ----------------------------------------------------------------------------
__global__ __launch_bounds__(256) void kmeans_kernel(const int* __restrict__ seq) {
    __shared__ float cent[Kcl * Cn];
    __shared__ float xsq[Tn];
    __shared__ float csq[Kcl];
    __shared__ int   sids[Tn];
    __shared__ int   cnt[Kcl];

    const int b    = blockIdx.x;
    const int tid  = threadIdx.x;
    const int lane = tid & 31;
    const int warp = tid >> 5;
    float* Xb = g_x + b * Tn * Cn;

    for (int i = tid; i < Kcl * Cn; i += 256) cent[i] = Xb[i];

    for (int r = 0; r < 32; r++) {
        int t = warp * 32 + r;
        float s = 0.f;
        #pragma unroll
        for (int j = 0; j < 8; j++) {
            float xv = Xb[t * Cn + lane + 32 * j];
            s += xv * xv;
        }
        s = warp_sum(s);
        if (lane == 0) xsq[t] = s;
    }
    __syncthreads();

    for (int iter = 0; iter <= 10; iter++) {
        if (tid < Kcl) {
            float s = 0.f;
            for (int c = 0; c < Cn; c++) { float v = cent[tid * Cn + c]; s += v * v; }
            csq[tid] = s;
        }
        __syncthreads();

        for (int r = 0; r < 32; r++) {
            int t = warp * 32 + r;
            float xv[8];
            #pragma unroll
            for (int j = 0; j < 8; j++) xv[j] = Xb[t * Cn + lane + 32 * j];
            float best = 3.4e38f; int bi = 0;
            #pragma unroll
            for (int k = 0; k < Kcl; k++) {
                float p = 0.f;
                #pragma unroll
                for (int j = 0; j < 8; j++) p += xv[j] * cent[k * Cn + lane + 32 * j];
                p = warp_sum(p);
                float d = xsq[t] - 2.0f * p + csq[k];
                if (d < best) { best = d; bi = k; }
            }
            if (lane == 0) sids[t] = bi;
        }
        __syncthreads();

        if (iter == 10) break;

        if (tid < Kcl) cnt[tid] = 0;
        __syncthreads();
        atomicAdd(&cnt[sids[tid]], 1);
        __syncthreads();

        {
            const int c = tid;
            float acc[Kcl];
            #pragma unroll
            for (int k = 0; k < Kcl; k++) acc[k] = 0.f;
            for (int t = 0; t < Tn; t++) {
                float v = Xb[t * Cn + c];
                int id = sids[t];
                #pragma unroll
                for (int k = 0; k < Kcl; k++) acc[k] += (id == k) ? v : 0.f;
            }
            __syncthreads();
            #pragma unroll
            for (int k = 0; k < Kcl; k++) {
                if (cnt[k] > 0) cent[k * Cn + c] = acc[k] / fmaxf((float)cnt[k], 1.0f);
            }
        }
        __syncthreads();
    }

    g_ids[b * Tn + tid] = sids[tid];

    // fused pad-mask + fp16 mirror
    __syncthreads();
    __half* Xh = g_xh + b * Tn * Cn;
    for (int idx = tid; idx < Tn * Cn; idx += 256) {
        int t = idx >> 8;
        float v = Xb[idx];
        if (seq[b * Tn + t] == 0) v = 0.0f;
        Xb[idx] = v;
        Xh[idx] = __float2half(v);
    }
}

// ----------------------------------------------------------------------------
// LayerNorm: warp per row; WF32 controls fp32 store
// ----------------------------------------------------------------------------
template <bool WF32>
__global__ __launch_bounds__(256) void ln_kernel(const float* __restrict__ in,
                                                 float* __restrict__ out,
                                                 __half* __restrict__ outh,
                                                 const float* __restrict__ g,
                                                 const float* __restrict__ bb) {
    int lane = threadIdx.x & 31, warp = threadIdx.x >> 5;
    int row = blockIdx.x * 8 + warp;
    const float* r = in + row * Cn;
    float v[8];
    #pragma unroll
    for (int j = 0; j < 8; j++) v[j] = r[lane + 32 * j];
    float s = 0.f;
    #pragma unroll
    for (int j = 0; j < 8; j++) s += v[j];
    s = warp_sum(s);
    float mu = s * (1.0f / 256.0f);
    float q = 0.f;
    #pragma unroll
    for (int j = 0; j < 8; j++) { float d = v[j] - mu; q += d * d; }
    q = warp_sum(q);
    float rinv = rsqrtf(q * (1.0f / 256.0f) + 1e-8f);
    #pragma unroll
    for (int j = 0; j < 8; j++) {
        int c = lane + 32 * j;
        float o = g[c] * (v[j] - mu) * rinv + bb[c];
        if (WF32) out[row * Cn + c] = o;
        outh[row * Cn + c] = __float2half(o);
    }
}

// ----------------------------------------------------------------------------
// fp16 tensor-core GEMM, 3-stage cp.async pipeline, ONE sync per K-iter.
// C[M, NSTR] = A[M,256] @ W[256,NSTR]; block tile 128x128, BK=32.
// MODE 0: half out = acc                  (Q projection)
// MODE 1: fp32 out = (acc + res) * keep
// MODE 2: half out = relu(acc + bias)
// MODE 3: fp32+half out = (acc+bias+res)*keep
// MODE 4: half out routed to g_Kh (blockIdx.x<2) / g_Vh (else), NSTR=512
// ----------------------------------------------------------------------------
__device__ __forceinline__ void ldsm4(uint32_t* r, uint32_t addr) {
    asm volatile("ldmatrix.sync.aligned.m8n8.x4.shared.b16 {%0,%1,%2,%3}, [%4];"
        : "=r"(r[0]), "=r"(r[1]), "=r"(r[2]), "=r"(r[3]) : "r"(addr));
}
__device__ __forceinline__ void ldsm4t(uint32_t* r, uint32_t addr) {
    asm volatile("ldmatrix.sync.aligned.m8n8.x4.trans.shared.b16 {%0,%1,%2,%3}, [%4];"
        : "=r"(r[0]), "=r"(r[1]), "=r"(r[2]), "=r"(r[3]) : "r"(addr));
}
__device__ __forceinline__ void mma16816(float* c, const uint32_t* a, const uint32_t* b) {
    asm volatile("mma.sync.aligned.m16n8k16.row.col.f32.f16.f16.f32 "
        "{%0,%1,%2,%3}, {%4,%5,%6,%7}, {%8,%9}, {%0,%1,%2,%3};"
        : "+f"(c[0]), "+f"(c[1]), "+f"(c[2]), "+f"(c[3])
        : "r"(a[0]), "r"(a[1]), "r"(a[2]), "r"(a[3]), "r"(b[0]), "r"(b[1]));
}

constexpr int BKg   = 32;
constexpr int AROW  = BKg + 8;           // 40 halves
constexpr int BROW  = 128 + 8;           // 136 halves
constexpr int ASTG  = 128 * AROW;        // halves per A stage
constexpr int BSTG  = BKg * BROW;        // halves per B stage
constexpr int GEMM_SMEM = (3 * (ASTG + BSTG)) * 2;   // bytes = 56832

template <int MODE, int NSTR>
__global__ __launch_bounds__(256, 2) void hgemm_kernel(const __half* __restrict__ A,
                                                       const __half* __restrict__ W,
                                                       float* __restrict__ Cout,
                                                       __half* __restrict__ CoutH,
                                                       const float* __restrict__ res,
                                                       const float* __restrict__ bias,
                                                       const int* __restrict__ seq) {
    extern __shared__ __align__(16) __half dsm[];
    __half* Asm = dsm;                  // 3 stages of [128][AROW]
    __half* Bsm = dsm + 3 * ASTG;       // 3 stages of [BKg][BROW]

    const int tid  = threadIdx.x;
    const int lane = tid & 31;
    const int warp = tid >> 5;
    const int wm   = warp >> 2;          // 0..1
    const int wn   = warp & 3;           // 0..3
    const int m0   = blockIdx.y * 128;
    const int n0   = blockIdx.x * 128;

    float acc[4][4][4];
    #pragma unroll
    for (int i = 0; i < 4; i++)
        #pragma unroll
        for (int j = 0; j < 4; j++)
            #pragma unroll
            for (int v = 0; v < 4; v++) acc[i][j][v] = 0.f;

    const int a_row0 = tid >> 2,          a_c0 = (tid & 3) * 8;
    const int a_row1 = (tid + 256) >> 2,  a_c1 = ((tid + 256) & 3) * 8;
    const int b_row0 = tid >> 4,          b_c0 = (tid & 15) * 8;
    const int b_row1 = (tid + 256) >> 4,  b_c1 = ((tid + 256) & 15) * 8;

    auto load_stage = [&](int s, int k0) {
        __half* As = Asm + s * ASTG;
        __half* Bs = Bsm + s * BSTG;
        cp_async16((uint32_t)__cvta_generic_to_shared(As + a_row0 * AROW + a_c0),
                   A + (m0 + a_row0) * 256 + k0 + a_c0);
        cp_async16((uint32_t)__cvta_generic_to_shared(As + a_row1 * AROW + a_c1),
                   A + (m0 + a_row1) * 256 + k0 + a_c1);
        cp_async16((uint32_t)__cvta_generic_to_shared(Bs + b_row0 * BROW + b_c0),
                   W + (k0 + b_row0) * NSTR + n0 + b_c0);
        cp_async16((uint32_t)__cvta_generic_to_shared(Bs + b_row1 * BROW + b_c1),
                   W + (k0 + b_row1) * NSTR + n0 + b_c1);
        cp_commit();
    };

    load_stage(0, 0);
    load_stage(1, BKg);

    for (int it = 0; it < 8; it++) {
        const int s = it % 3;
        if (it < 6) cp_wait<1>(); else cp_wait<0>();
        __syncthreads();
        if (it < 6) load_stage((it + 2) % 3, (it + 2) * BKg);

        uint32_t as_base = (uint32_t)__cvta_generic_to_shared(Asm + s * ASTG);
        uint32_t bs_base = (uint32_t)__cvta_generic_to_shared(Bsm + s * BSTG);

        #pragma unroll
        for (int kk = 0; kk < BKg; kk += 16) {
            uint32_t aF[4][4];
            uint32_t bF[4][2];
            #pragma unroll
            for (int mt = 0; mt < 4; mt++) {
                int row = wm * 64 + mt * 16 + (lane & 15);
                int col = kk + (lane >> 4) * 8;
                ldsm4(aF[mt], as_base + (uint32_t)((row * AROW + col) * 2));
            }
            #pragma unroll
            for (int np = 0; np < 2; np++) {
                int k = kk + (lane & 15);
                int n = wn * 32 + np * 16 + (lane >> 4) * 8;
                uint32_t r[4];
                ldsm4t(r, bs_base + (uint32_t)((k * BROW + n) * 2));
                bF[np * 2][0] = r[0]; bF[np * 2][1] = r[1];
                bF[np * 2 + 1][0] = r[2]; bF[np * 2 + 1][1] = r[3];
            }
            #pragma unroll
            for (int mt = 0; mt < 4; mt++)
                #pragma unroll
                for (int nt = 0; nt < 4; nt++)
                    mma16816(acc[mt][nt], aF[mt], bF[nt]);
        }
    }

    // epilogue
    const int gid = lane >> 2, tig = lane & 3;
    #pragma unroll
    for (int mt = 0; mt < 4; mt++) {
        #pragma unroll
        for (int hr = 0; hr < 2; hr++) {
            int m = m0 + wm * 64 + mt * 16 + gid + hr * 8;
            float keep = 1.0f;
            if (MODE == 1 || MODE == 3) keep = (seq[m] != 0) ? 1.0f : 0.0f;
            #pragma unroll
            for (int nt = 0; nt < 4; nt++) {
                int n = n0 + wn * 32 + nt * 8 + tig * 2;
                float v0 = acc[mt][nt][hr * 2 + 0];
                float v1 = acc[mt][nt][hr * 2 + 1];
                if (MODE == 2 || MODE == 3) { v0 += bias[n]; v1 += bias[n + 1]; }
                if (MODE == 1 || MODE == 3) {
                    const float2 rv = *(const float2*)(res + m * 256 + n);
                    v0 = (v0 + rv.x) * keep;
                    v1 = (v1 + rv.y) * keep;
                }
                if (MODE == 2) { v0 = fmaxf(v0, 0.f); v1 = fmaxf(v1, 0.f); }
                if (MODE == 4) {
                    __half* dst = (n < 256) ? (g_Kh + m * 256 + n)
                                            : (g_Vh + m * 256 + (n - 256));
                    *(__half2*)dst = __floats2half2_rn(v0, v1);
                } else if (MODE == 0 || MODE == 2) {
                    *(__half2*)(CoutH + m * 256 + n) = __floats2half2_rn(v0, v1);
                } else {
                    *(float2*)(Cout + m * 256 + n) = make_float2(v0, v1);
                    if (MODE == 3)
                        *(__half2*)(CoutH + m * 256 + n) = __floats2half2_rn(v0, v1);
                }
            }
        }
    }
}

// ----------------------------------------------------------------------------
// Cluster-bucketed attention. fp16 Q/K/V in gmem; fp32 smem K/V; fp32 math.
// ----------------------------------------------------------------------------
__global__ __launch_bounds__(256, 1) void attn_kernel(const int* __restrict__ seq) {
    extern __shared__ float sm[];
    float* Ks = sm;                    // [256][64]
    float* Vs = sm + Tn * DHn;
    __shared__ int sids[Tn];
    __shared__ int klist[Tn];
    __shared__ int cnt[Kcl], off[Kcl], cur[Kcl];

    const int b = blockIdx.x >> 2;     // Hn = 4
    const int h = blockIdx.x & 3;
    const int tid = threadIdx.x;

    const __half2* Kg = (const __half2*)g_Kh;
    const __half2* Vg = (const __half2*)g_Vh;
    for (int idx = tid; idx < Tn * 32; idx += 256) {
        int t = idx >> 5, d2 = idx & 31;
        int gi2 = ((b * Tn + t) * Cn + h * DHn) / 2 + d2;
        float2 kf = __half22float2(Kg[gi2]);
        float2 vf = __half22float2(Vg[gi2]);
        Ks[t * DHn + d2 * 2]     = kf.x;
        Ks[t * DHn + d2 * 2 + 1] = kf.y;
        Vs[t * DHn + d2 * 2]     = vf.x;
        Vs[t * DHn + d2 * 2 + 1] = vf.y;
    }
    sids[tid] = g_ids[b * Tn + tid];
    if (tid < Kcl) cnt[tid] = 0;
    __syncthreads();
    atomicAdd(&cnt[sids[tid]], 1);
    __syncthreads();
    if (tid == 0) {
        int acc = 0;
        for (int k = 0; k < Kcl; k++) { off[k] = acc; cur[k] = acc; acc += cnt[k]; }
    }
    __syncthreads();
    {
        int c = sids[tid];
        int pos = atomicAdd(&cur[c], 1);
        klist[pos] = tid;
    }
    __syncthreads();

    const int q = klist[tid];
    const int c = sids[q];
    const bool qvalid = (seq[b * Tn + q] != 0);

    float4 qv[16];
    {
        const __half2* qp = (const __half2*)(g_Qh + (b * Tn + q) * Cn + h * DHn);
        #pragma unroll
        for (int j = 0; j < 16; j++) {
            float2 f0 = __half22float2(qp[j * 2]);
            float2 f1 = __half22float2(qp[j * 2 + 1]);
            qv[j] = make_float4(f0.x, f0.y, f1.x, f1.y);
        }
    }

    float m = -1e30f, ssum = 0.f;
    float4 accv[16];
    #pragma unroll
    for (int j = 0; j < 16; j++) accv[j] = make_float4(0.f, 0.f, 0.f, 0.f);

    if (qvalid) {
        const int cbeg = off[c];
        const int cend = cbeg + cnt[c];
        for (int j = cbeg; j < cend; j++) {
            int k = klist[j];
            const float4* kp = (const float4*)&Ks[k * DHn];
            float dot = 0.f;
            #pragma unroll
            for (int jj = 0; jj < 16; jj++) {
                float4 kvv = kp[jj];
                dot += qv[jj].x * kvv.x + qv[jj].y * kvv.y + qv[jj].z * kvv.z + qv[jj].w * kvv.w;
            }
            float s = dot * 0.125f;
            float nm = fmaxf(m, s);
            float cs = __expf(m - nm);
            float p  = __expf(s - nm);
            ssum = ssum * cs + p;
            const float4* vp = (const float4*)&Vs[k * DHn];
            #pragma unroll
            for (int jj = 0; jj < 16; jj++) {
                float4 vv = vp[jj];
                accv[jj].x = accv[jj].x * cs + p * vv.x;
                accv[jj].y = accv[jj].y * cs + p * vv.y;
                accv[jj].z = accv[jj].z * cs + p * vv.z;
                accv[jj].w = accv[jj].w * cs + p * vv.w;
            }
            m = nm;
        }
    }

    float inv = qvalid ? (1.0f / ssum) : 0.0f;
    __half2* op = (__half2*)(g_attnh + (b * Tn + q) * Cn + h * DHn);
    #pragma unroll
    for (int j = 0; j < 16; j++) {
        op[j * 2 + 0] = __floats2half2_rn(accv[j].x * inv, accv[j].y * inv);
        op[j * 2 + 1] = __floats2half2_rn(accv[j].z * inv, accv[j].w * inv);
    }
}

// ----------------------------------------------------------------------------
// Fused final LayerNorm + logits
// ----------------------------------------------------------------------------
__global__ __launch_bounds__(256) void lnlogits_kernel(const int* __restrict__ uid,
                                                       const int* __restrict__ pos_seqs,
                                                       const int* __restrict__ neg_seqs,
                                                       const float* __restrict__ item_emb,
                                                       const float* __restrict__ user_emb,
                                                       const float* __restrict__ lnfg,
                                                       const float* __restrict__ lnfb,
                                                       float* __restrict__ out) {
    int lane = threadIdx.x & 31, warp = threadIdx.x >> 5;
    int i = blockIdx.x * 8 + warp;
    int b = i >> 8;
    const float* r = g_x + i * Cn;
    float v[8];
    #pragma unroll
    for (int j = 0; j < 8; j++) v[j] = r[lane + 32 * j];
    float s = 0.f;
    #pragma unroll
    for (int j = 0; j < 8; j++) s += v[j];
    s = warp_sum(s);
    float mu = s * (1.0f / 256.0f);
    float q = 0.f;
    #pragma unroll
    for (int j = 0; j < 8; j++) { float d = v[j] - mu; q += d * d; }
    q = warp_sum(q);
    float rinv = rsqrtf(q * (1.0f / 256.0f) + 1e-8f);

    const float* pe = item_emb + pos_seqs[i] * ITEM_H;
    const float* ne = item_emb + neg_seqs[i] * ITEM_H;
    const float* ul = user_emb + uid[b] * USER_H;

    float sp = 0.f, sn = 0.f;
    #pragma unroll
    for (int j = 0; j < 8; j++) {
        int c = lane + 32 * j;
        float o = lnfg[c] * (v[j] - mu) * rinv + lnfb[c];
        if (c < ITEM_H) {
            sp += o * pe[c];
            sn += o * ne[c];
        } else {
            float u = ul[c - ITEM_H];
            sp += o * u;
            sn += o * u;
        }
    }
    sp = warp_sum(sp);
    sn = warp_sum(sn);
    if (lane == 0) {
        out[i]        = sp;
        out[NTOK + i] = sn;
    }
}

// ----------------------------------------------------------------------------
// Launch
// ----------------------------------------------------------------------------
extern "C" void kernel_launch(void* const* d_in, const int* in_sizes, int n_in,
                              void* d_out, int out_size) {
    const int*   uid      = (const int*)d_in[0];
    const int*   seq      = (const int*)d_in[1];
    const int*   pos_seqs = (const int*)d_in[2];
    const int*   neg_seqs = (const int*)d_in[3];
    const float* item_emb = (const float*)d_in[4];
    const float* user_emb = (const float*)d_in[5];
    const float* pos_emb  = (const float*)d_in[6];
    const float* Wq = (const float*)d_in[7];
    const float* Wk = (const float*)d_in[8];
    const float* Wv = (const float*)d_in[9];
    const float* Wo = (const float*)d_in[10];
    const float* ln1g = (const float*)d_in[11];
    const float* ln1b = (const float*)d_in[12];
    const float* ln2g = (const float*)d_in[13];
    const float* ln2b = (const float*)d_in[14];
    const float* W1 = (const float*)d_in[15];
    const float* b1 = (const float*)d_in[16];
    const float* W2 = (const float*)d_in[17];
    const float* b2 = (const float*)d_in[18];
    const float* lnfg = (const float*)d_in[19];
    const float* lnfb = (const float*)d_in[20];
    float* out = (float*)d_out;

    float *px, *pqin;
    __half *pxh, *pqinh, *pattnh, *ph1h, *pwh, *pwkv, *pQh;
    cudaGetSymbolAddress((void**)&px,     g_x);
    cudaGetSymbolAddress((void**)&pqin,   g_qin);
    cudaGetSymbolAddress((void**)&pxh,    g_xh);
    cudaGetSymbolAddress((void**)&pqinh,  g_qinh);
    cudaGetSymbolAddress((void**)&pattnh, g_attnh);
    cudaGetSymbolAddress((void**)&ph1h,   g_h1h);
    cudaGetSymbolAddress((void**)&pwh,    g_Wh);
    cudaGetSymbolAddress((void**)&pwkv,   g_Wkvh);
    cudaGetSymbolAddress((void**)&pQh,    g_Qh);

    const int WSZ = Cn * Cn;
    const int ASZ = Ln * WSZ;

    const int attn_smem = 2 * Tn * DHn * (int)sizeof(float);  // 128 KB
    cudaFuncSetAttribute(attn_kernel, cudaFuncAttributeMaxDynamicSharedMemorySize, attn_smem);
    cudaFuncSetAttribute(hgemm_kernel<0, 256>, cudaFuncAttributeMaxDynamicSharedMemorySize, GEMM_SMEM);
    cudaFuncSetAttribute(hgemm_kernel<1, 256>, cudaFuncAttributeMaxDynamicSharedMemorySize, GEMM_SMEM);
    cudaFuncSetAttribute(hgemm_kernel<2, 256>, cudaFuncAttributeMaxDynamicSharedMemorySize, GEMM_SMEM);
    cudaFuncSetAttribute(hgemm_kernel<3, 256>, cudaFuncAttributeMaxDynamicSharedMemorySize, GEMM_SMEM);
    cudaFuncSetAttribute(hgemm_kernel<4, 512>, cudaFuncAttributeMaxDynamicSharedMemorySize, GEMM_SMEM);

    const dim3 ggrid(Cn / 128, NTOK / 128);       // 2 x 1024
    const dim3 kvgrid(2 * Cn / 128, NTOK / 128);  // 4 x 1024

    embed_kernel<<<NC / 256, 256>>>(uid, seq, item_emb, user_emb, pos_emb);   // 0
    convw_kernel<<<(4 * ASZ) / 256, 256>>>(Wq, Wo, W1, W2);                   // 1
    convkv_kernel<<<(Ln * Cn * 2 * Cn) / 256, 256>>>(Wk, Wv);                 // 2
    kmeans_kernel<<<Bn, 256>>>(seq);                                          // 3 (profiled)

    for (int l = 0; l < Ln; l++) {
        const __half* whq  = pwh + 0 * ASZ + l * WSZ;
        const __half* who  = pwh + 1 * ASZ + l * WSZ;
        const __half* wh1  = pwh + 2 * ASZ + l * WSZ;
        const __half* wh2  = pwh + 3 * ASZ + l * WSZ;
        const __half* whkv = pwkv + l * Cn * 2 * Cn;

        // fused K+V projection
        hgemm_kernel<4, 512><<<kvgrid, 256, GEMM_SMEM>>>(pxh, whkv, nullptr, nullptr, nullptr, nullptr, nullptr);
        // q_in = LN1(x): fp32 (residual) + fp16
        ln_kernel<true><<<NTOK / 8, 256>>>(px, pqin, pqinh, ln1g + l * Cn, ln1b + l * Cn);
        hgemm_kernel<0, 256><<<ggrid, 256, GEMM_SMEM>>>(pqinh, whq, nullptr, pQh, nullptr, nullptr, nullptr);
        // bucketed attention
        attn_kernel<<<Bn * Hn, 256, attn_smem>>>(seq);
        // x = (q_in + attn @ Wo) * keep
        hgemm_kernel<1, 256><<<ggrid, 256, GEMM_SMEM>>>(pattnh, who, px, nullptr, pqin, nullptr, seq);
        // f = LN2(x): fp16 only
        ln_kernel<false><<<NTOK / 8, 256>>>(px, nullptr, pqinh, ln2g + l * Cn, ln2b + l * Cn);
        // h1 = relu(f @ W1 + b1)
        hgemm_kernel<2, 256><<<ggrid, 256, GEMM_SMEM>>>(pqinh, wh1, nullptr, ph1h, nullptr, b1 + l * Cn, nullptr);
        // x = (x + h1 @ W2 + b2) * keep
        hgemm_kernel<3, 256><<<ggrid, 256, GEMM_SMEM>>>(ph1h, wh2, px, pxh, px, b2 + l * Cn, seq);
    }

    // fused final LN + logits
    lnlogits_kernel<<<NTOK / 8, 256>>>(uid, pos_seqs, neg_seqs, item_emb, user_emb,
                                       lnfg, lnfb, out);
}